// round 6
// baseline (speedup 1.0000x reference)
#include <cuda_runtime.h>
#include <math.h>

#define N_NODES 100000
#define N_FEATS 2048
#define HID 64
#define NLAB 40

// Scratch (no allocations allowed): 25.6 + 25.6 + 16 MB
__device__ __align__(16) float g_h1[N_NODES * HID];   // after feature SpMM + b1
__device__ __align__(16) float g_h2[N_NODES * HID];   // after adjacency SpMM
__device__ __align__(16) float g_z1[N_NODES * NLAB];  // after dense layer

__device__ __forceinline__ void red_add_v4(float* p, float a, float b, float c, float d) {
    asm volatile("red.global.add.v4.f32 [%0], {%1,%2,%3,%4};"
                 :: "l"(p), "f"(a), "f"(b), "f"(c), "f"(d) : "memory");
}

__device__ __forceinline__ int clamp_i(int i, int n) {
    i = i < 0 ? 0 : i;
    return i >= n ? n - 1 : i;
}

// Init with float4 stores: h1 rows = b1 broadcast, h2 = 0, out = 0
__global__ void k_init(const float* __restrict__ b1, float* __restrict__ out) {
    int i = blockIdx.x * blockDim.x + threadIdx.x;   // float4 index
    if (i < N_NODES * HID / 4) {
        float4 b = __ldg((const float4*)b1 + (i & 15));
        ((float4*)g_h1)[i] = b;
        ((float4*)g_h2)[i] = make_float4(0.f, 0.f, 0.f, 0.f);
    }
    if (i < N_NODES * NLAB / 4)
        ((float4*)out)[i] = make_float4(0.f, 0.f, 0.f, 0.f);
}

// Feature SpMM: h1[row] += val * W1[col, :]   (16 threads per nnz, float4 each)
__global__ void k_feat(const int* __restrict__ fi, const float* __restrict__ fv,
                       const float* __restrict__ W1, int nnz) {
    int t = blockIdx.x * blockDim.x + threadIdx.x;
    if (t >= nnz * 16) return;
    int e = t >> 4, q = t & 15;
    int row = clamp_i(__ldg(&fi[e]), N_NODES);
    int col = clamp_i(__ldg(&fi[nnz + e]), N_FEATS);
    float v = __ldg(&fv[e]);
    float4 w = __ldg((const float4*)(W1 + (size_t)col * HID) + q);
    red_add_v4(&g_h1[(size_t)row * HID + q * 4], v * w.x, v * w.y, v * w.z, v * w.w);
}

// Adjacency SpMM (64-wide): h2[row] += w * h1[col]
__global__ void k_edge64(const int* __restrict__ ei, const float* __restrict__ ew, int ne) {
    int t = blockIdx.x * blockDim.x + threadIdx.x;
    if (t >= ne * 16) return;
    int e = t >> 4, q = t & 15;
    int row = clamp_i(__ldg(&ei[e]), N_NODES);
    int col = clamp_i(__ldg(&ei[ne + e]), N_NODES);
    float w = __ldg(&ew[e]);
    float4 s = __ldg((const float4*)(g_h1 + (size_t)col * HID) + q);
    red_add_v4(&g_h2[(size_t)row * HID + q * 4], w * s.x, w * s.y, w * s.z, w * s.w);
}

// Dense layer: z1 = relu(h2) @ W2 + b2.
// 64 nodes/block, 256 threads: 4 threads per node, 10 labels each.
// W2 transposed in smem (stride 68, 16B-aligned) -> float4 LDS feeding FFMAs.
#define DN 64
#define PADK 68
__global__ __launch_bounds__(256) void k_dense(const float* __restrict__ W2,
                                               const float* __restrict__ b2) {
    __shared__ float sW2t[NLAB * PADK];   // [j][k]
    __shared__ float sb2[NLAB];
    __shared__ float sh[DN * PADK];       // [node_local][k], relu applied
    int tid = threadIdx.x;

    for (int i = tid; i < HID * NLAB; i += 256) {
        int k = i / NLAB, j = i - k * NLAB;
        sW2t[j * PADK + k] = W2[i];
    }
    if (tid < NLAB) sb2[tid] = b2[tid];

    int base4 = blockIdx.x * DN * (HID / 4);           // float4 base into g_h2
    for (int v = tid; v < DN * (HID / 4); v += 256) {
        int g4 = base4 + v;
        float4 x = (g4 < N_NODES * HID / 4) ? ((const float4*)g_h2)[g4]
                                            : make_float4(0.f, 0.f, 0.f, 0.f);
        x.x = fmaxf(x.x, 0.f); x.y = fmaxf(x.y, 0.f);
        x.z = fmaxf(x.z, 0.f); x.w = fmaxf(x.w, 0.f);
        int row = v >> 4, col4 = (v & 15) * 4;         // 16 float4 per row
        *(float4*)&sh[row * PADK + col4] = x;
    }
    __syncthreads();

    int nl = tid >> 2;                  // node_local 0..63
    int node = blockIdx.x * DN + nl;
    if (node >= N_NODES) return;
    int j0 = (tid & 3) * 10;

    float acc[10];
#pragma unroll
    for (int j = 0; j < 10; j++) acc[j] = sb2[j0 + j];

#pragma unroll
    for (int k4 = 0; k4 < HID; k4 += 4) {
        float4 h = *(const float4*)&sh[nl * PADK + k4];
#pragma unroll
        for (int j = 0; j < 10; j++) {
            float4 w = *(const float4*)&sW2t[(j0 + j) * PADK + k4];
            acc[j] += h.x * w.x + h.y * w.y + h.z * w.z + h.w * w.w;
        }
    }

    float* zp = g_z1 + (size_t)node * NLAB + j0;
#pragma unroll
    for (int j = 0; j < 10; j += 2)
        *(float2*)(zp + j) = make_float2(acc[j], acc[j + 1]);
}

// Adjacency SpMM (40-wide): out[row] += w * z1[col]. Thread per (edge, float4).
__global__ void k_edge40(const int* __restrict__ ei, const float* __restrict__ ew,
                         float* __restrict__ out, int ne) {
    int t = blockIdx.x * blockDim.x + threadIdx.x;
    if (t >= ne * 10) return;
    int e = t / 10;
    int q = t - e * 10;
    int row = clamp_i(__ldg(&ei[e]), N_NODES);
    int col = clamp_i(__ldg(&ei[ne + e]), N_NODES);
    float w = __ldg(&ew[e]);
    float4 s = __ldg((const float4*)(g_z1 + (size_t)col * NLAB) + q);
    red_add_v4(out + (size_t)row * NLAB + q * 4, w * s.x, w * s.y, w * s.z, w * s.w);
}

// In-place log-softmax over 40 labels: one warp per node.
__global__ void k_lsm(float* __restrict__ out) {
    int gw = (blockIdx.x * blockDim.x + threadIdx.x) >> 5;
    int lane = threadIdx.x & 31;
    if (gw >= N_NODES) return;
    float* r = out + (size_t)gw * NLAB;
    float v0 = r[lane];
    float v1 = (lane < 8) ? r[32 + lane] : -1e30f;
    float m = fmaxf(v0, v1);
#pragma unroll
    for (int o = 16; o; o >>= 1) m = fmaxf(m, __shfl_xor_sync(0xFFFFFFFFu, m, o));
    float s = expf(v0 - m) + ((lane < 8) ? expf(v1 - m) : 0.0f);
#pragma unroll
    for (int o = 16; o; o >>= 1) s += __shfl_xor_sync(0xFFFFFFFFu, s, o);
    float l = m + logf(s);
    r[lane] = v0 - l;
    if (lane < 8) r[32 + lane] = v1 - l;
}

extern "C" void kernel_launch(void* const* d_in, const int* in_sizes, int n_in,
                              void* d_out, int out_size) {
    // Bind inputs by element count (all eight are pairwise distinct) so we do
    // not depend on metadata ordering. Indices are int32 (JAX x64 disabled).
    const int* fi = 0; const float* fv = 0;
    const int* ei = 0; const float* ew = 0;
    const float *W1 = 0, *b1 = 0, *W2 = 0, *b2 = 0;
    int nnz = 0, ne = 0;
    for (int i = 0; i < n_in; i++) {
        int s = in_sizes[i];
        const void* p = d_in[i];
        if (s == 2 * 2500000)            { fi = (const int*)p; }
        else if (s == 2500000)           { fv = (const float*)p; nnz = s; }
        else if (s == 2 * 1700000)       { ei = (const int*)p; }
        else if (s == 1700000)           { ew = (const float*)p; ne = s; }
        else if (s == N_FEATS * HID)     { W1 = (const float*)p; }
        else if (s == HID)               { b1 = (const float*)p; }
        else if (s == HID * NLAB)        { W2 = (const float*)p; }
        else if (s == NLAB)              { b2 = (const float*)p; }
    }
    float* out = (float*)d_out;

    k_init<<<(N_NODES * HID / 4 + 255) / 256, 256>>>(b1, out);
    k_feat<<<(nnz * 16 + 255) / 256, 256>>>(fi, fv, W1, nnz);
    k_edge64<<<(ne * 16 + 255) / 256, 256>>>(ei, ew, ne);
    k_dense<<<(N_NODES + DN - 1) / DN, 256>>>(W2, b2);
    k_edge40<<<(ne * 10 + 255) / 256, 256>>>(ei, ew, out, ne);
    k_lsm<<<(N_NODES * 32 + 255) / 256, 256>>>(out);
}

// round 7
// speedup vs baseline: 1.9070x; 1.9070x over previous
#include <cuda_runtime.h>
#include <math.h>

#define N_NODES 100000
#define N_FEATS 2048
#define HID 64
#define NLAB 40
#define N_SEG (2 * N_NODES)          // feat rows [0,100K) + edge rows [100K,200K)
#define MAX_NNZ 2500000
#define MAX_NE  1700000
#define NBLK 196                     // ceil(N_SEG / 1024)

// ---- scratch (static: no allocations allowed) ----
__device__ __align__(16) float g_h1[N_NODES * HID];
__device__ __align__(16) float g_h2[N_NODES * HID];   // relu'ed after edge SpMM
__device__ __align__(16) float g_z1[N_NODES * NLAB];
__device__ int  g_cnt[N_SEG];
__device__ int  g_off[N_SEG];
__device__ int  g_bsum[256];
__device__ int  g_start[N_SEG];
__device__ int  g_cursor[N_SEG];
__device__ __align__(8) int2 g_fbuf[MAX_NNZ];         // (col, val bits) grouped by row
__device__ __align__(8) int2 g_ebuf[MAX_NE];          // (col, w bits) grouped by row

__device__ __forceinline__ int clamp_i(int i, int n) {
    i = i < 0 ? 0 : i;
    return i >= n ? n - 1 : i;
}

// ---------------- CSR build: zero, histogram, scan, scatter ----------------
__global__ void k_zero() {
    int i = blockIdx.x * blockDim.x + threadIdx.x;
    if (i < N_SEG) g_cnt[i] = 0;
}

__global__ void k_hist_f(const int* __restrict__ fi, int nnz) {
    int e = blockIdx.x * blockDim.x + threadIdx.x;
    if (e < nnz) atomicAdd(&g_cnt[clamp_i(__ldg(&fi[e]), N_NODES)], 1);
}

__global__ void k_hist_e(const int* __restrict__ ei, int ne) {
    int e = blockIdx.x * blockDim.x + threadIdx.x;
    if (e < ne) atomicAdd(&g_cnt[N_NODES + clamp_i(__ldg(&ei[e]), N_NODES)], 1);
}

__global__ __launch_bounds__(1024) void k_scan1() {
    __shared__ int s[2][1024];
    int tid = threadIdx.x;
    int i = blockIdx.x * 1024 + tid;
    s[0][tid] = (i < N_SEG) ? g_cnt[i] : 0;
    __syncthreads();
    int cur = 0;
#pragma unroll
    for (int d = 1; d < 1024; d <<= 1) {
        int v = s[cur][tid];
        if (tid >= d) v += s[cur][tid - d];
        s[cur ^ 1][tid] = v;
        __syncthreads();
        cur ^= 1;
    }
    if (i < N_SEG) g_off[i] = s[cur][tid];
    if (tid == 1023) g_bsum[blockIdx.x] = s[cur][1023];
}

__global__ __launch_bounds__(256) void k_scan2() {
    __shared__ int s[2][256];
    int t = threadIdx.x;
    s[0][t] = (t < NBLK) ? g_bsum[t] : 0;
    __syncthreads();
    int cur = 0;
#pragma unroll
    for (int d = 1; d < 256; d <<= 1) {
        int v = s[cur][t];
        if (t >= d) v += s[cur][t - d];
        s[cur ^ 1][t] = v;
        __syncthreads();
        cur ^= 1;
    }
    if (t < NBLK) g_bsum[t] = s[cur][t];
}

__global__ void k_scan3() {
    int i = blockIdx.x * blockDim.x + threadIdx.x;
    if (i >= N_SEG) return;
    int b = i >> 10;
    int base = b ? g_bsum[b - 1] : 0;
    int st = g_off[i] + base - g_cnt[i];     // exclusive start
    g_start[i] = st;
    g_cursor[i] = st;
}

__global__ void k_scat_f(const int* __restrict__ fi, const float* __restrict__ fv, int nnz) {
    int e = blockIdx.x * blockDim.x + threadIdx.x;
    if (e >= nnz) return;
    int row = clamp_i(__ldg(&fi[e]), N_NODES);
    int col = clamp_i(__ldg(&fi[nnz + e]), N_FEATS);
    float v = __ldg(&fv[e]);
    int pos = atomicAdd(&g_cursor[row], 1);
    g_fbuf[pos] = make_int2(col, __float_as_int(v));
}

__global__ void k_scat_e(const int* __restrict__ ei, const float* __restrict__ ew, int ne, int nnz) {
    int e = blockIdx.x * blockDim.x + threadIdx.x;
    if (e >= ne) return;
    int row = clamp_i(__ldg(&ei[e]), N_NODES);
    int col = clamp_i(__ldg(&ei[ne + e]), N_NODES);
    float w = __ldg(&ew[e]);
    int pos = atomicAdd(&g_cursor[N_NODES + row], 1) - nnz;
    g_ebuf[pos] = make_int2(col, __float_as_int(w));
}

// ---------------- gather-only SpMMs (16 lanes per row, float4 per lane) ----------------
// h1[row] = b1 + sum_i val_i * W1[col_i, :]
__global__ __launch_bounds__(256) void k_feat_csr(const float* __restrict__ W1,
                                                  const float* __restrict__ b1) {
    int tid = threadIdx.x;
    int row = blockIdx.x * 16 + (tid >> 4);
    int q = tid & 15;
    if (row >= N_NODES) return;
    int s = g_start[row];
    int n = g_cnt[row];
    float4 acc = __ldg((const float4*)b1 + q);
    for (int i = 0; i < n; i++) {
        int2 p = __ldg(&g_fbuf[s + i]);
        float v = __int_as_float(p.y);
        float4 w = __ldg((const float4*)(W1 + (size_t)p.x * HID) + q);
        acc.x += v * w.x; acc.y += v * w.y; acc.z += v * w.z; acc.w += v * w.w;
    }
    *((float4*)(g_h1 + (size_t)row * HID) + q) = acc;
}

// h2[row] = relu( sum_i w_i * h1[col_i] )   (relu fused into the store)
__global__ __launch_bounds__(256) void k_edge64_csr(int nnz) {
    int tid = threadIdx.x;
    int row = blockIdx.x * 16 + (tid >> 4);
    int q = tid & 15;
    if (row >= N_NODES) return;
    int s = g_start[N_NODES + row] - nnz;
    int n = g_cnt[N_NODES + row];
    float4 acc = make_float4(0.f, 0.f, 0.f, 0.f);
    for (int i = 0; i < n; i++) {
        int2 p = __ldg(&g_ebuf[s + i]);
        float w = __int_as_float(p.y);
        float4 h = __ldg((const float4*)(g_h1 + (size_t)p.x * HID) + q);
        acc.x += w * h.x; acc.y += w * h.y; acc.z += w * h.z; acc.w += w * h.w;
    }
    acc.x = fmaxf(acc.x, 0.f); acc.y = fmaxf(acc.y, 0.f);
    acc.z = fmaxf(acc.z, 0.f); acc.w = fmaxf(acc.w, 0.f);
    *((float4*)(g_h2 + (size_t)row * HID) + q) = acc;
}

// ---------------- dense: z1 = h2 @ W2 + b2 (h2 already relu'ed) ----------------
// 4 nodes x 10 labels per thread; h via direct LDG (L2-resident); W2^T in smem.
#define PADK 68
__global__ __launch_bounds__(256) void k_dense(const float* __restrict__ W2,
                                               const float* __restrict__ b2) {
    __shared__ float sW2t[NLAB * PADK];   // [j][k]
    __shared__ float sb2[NLAB];
    int tid = threadIdx.x;
    for (int i = tid; i < HID * NLAB; i += 256) {
        int k = i / NLAB, j = i - k * NLAB;
        sW2t[j * PADK + k] = W2[i];
    }
    if (tid < NLAB) sb2[tid] = b2[tid];
    __syncthreads();

    int j0 = (tid & 3) * 10;
    int n0 = (blockIdx.x * 64 + (tid >> 2)) * 4;

    float acc[4][10];
#pragma unroll
    for (int nn = 0; nn < 4; nn++)
#pragma unroll
        for (int j = 0; j < 10; j++) acc[nn][j] = sb2[j0 + j];

#pragma unroll
    for (int k4 = 0; k4 < HID; k4 += 4) {
        float4 h[4];
#pragma unroll
        for (int nn = 0; nn < 4; nn++) {
            int nd = n0 + nn;
            h[nn] = (nd < N_NODES) ? __ldg((const float4*)(g_h2 + (size_t)nd * HID + k4))
                                   : make_float4(0.f, 0.f, 0.f, 0.f);
        }
#pragma unroll
        for (int j = 0; j < 10; j++) {
            float4 w = *(const float4*)&sW2t[(j0 + j) * PADK + k4];
#pragma unroll
            for (int nn = 0; nn < 4; nn++)
                acc[nn][j] += h[nn].x * w.x + h[nn].y * w.y + h[nn].z * w.z + h[nn].w * w.w;
        }
    }
#pragma unroll
    for (int nn = 0; nn < 4; nn++) {
        int nd = n0 + nn;
        if (nd >= N_NODES) break;
        float* zp = g_z1 + (size_t)nd * NLAB + j0;
#pragma unroll
        for (int j = 0; j < 10; j += 2)
            *(float2*)(zp + j) = make_float2(acc[nn][j], acc[nn][j + 1]);
    }
}

// ---------------- final propagate: out[row] = sum w_i * z1[col_i] ----------------
__global__ __launch_bounds__(256) void k_edge40_csr(float* __restrict__ out, int nnz) {
    int tid = threadIdx.x;
    int row = blockIdx.x * 16 + (tid >> 4);
    int q = tid & 15;
    if (row >= N_NODES) return;
    int s = g_start[N_NODES + row] - nnz;
    int n = g_cnt[N_NODES + row];
    float4 acc = make_float4(0.f, 0.f, 0.f, 0.f);
    for (int i = 0; i < n; i++) {
        int2 p = __ldg(&g_ebuf[s + i]);
        float w = __int_as_float(p.y);
        if (q < 10) {
            float4 z = __ldg((const float4*)(g_z1 + (size_t)p.x * NLAB) + q);
            acc.x += w * z.x; acc.y += w * z.y; acc.z += w * z.z; acc.w += w * z.w;
        }
    }
    if (q < 10)
        *((float4*)(out + (size_t)row * NLAB) + q) = acc;
}

// ---------------- in-place log-softmax over 40 labels (warp per node) ----------------
__global__ void k_lsm(float* __restrict__ out) {
    int gw = (blockIdx.x * blockDim.x + threadIdx.x) >> 5;
    int lane = threadIdx.x & 31;
    if (gw >= N_NODES) return;
    float* r = out + (size_t)gw * NLAB;
    float v0 = r[lane];
    float v1 = (lane < 8) ? r[32 + lane] : -1e30f;
    float m = fmaxf(v0, v1);
#pragma unroll
    for (int o = 16; o; o >>= 1) m = fmaxf(m, __shfl_xor_sync(0xFFFFFFFFu, m, o));
    float s = expf(v0 - m) + ((lane < 8) ? expf(v1 - m) : 0.0f);
#pragma unroll
    for (int o = 16; o; o >>= 1) s += __shfl_xor_sync(0xFFFFFFFFu, s, o);
    float l = m + logf(s);
    r[lane] = v0 - l;
    if (lane < 8) r[32 + lane] = v1 - l;
}

extern "C" void kernel_launch(void* const* d_in, const int* in_sizes, int n_in,
                              void* d_out, int out_size) {
    // Bind inputs by element count (pairwise distinct); indices are int32.
    const int* fi = 0; const float* fv = 0;
    const int* ei = 0; const float* ew = 0;
    const float *W1 = 0, *b1 = 0, *W2 = 0, *b2 = 0;
    int nnz = 0, ne = 0;
    for (int i = 0; i < n_in; i++) {
        int s = in_sizes[i];
        const void* p = d_in[i];
        if (s == 2 * MAX_NNZ)            { fi = (const int*)p; }
        else if (s == MAX_NNZ)           { fv = (const float*)p; nnz = s; }
        else if (s == 2 * MAX_NE)        { ei = (const int*)p; }
        else if (s == MAX_NE)            { ew = (const float*)p; ne = s; }
        else if (s == N_FEATS * HID)     { W1 = (const float*)p; }
        else if (s == HID)               { b1 = (const float*)p; }
        else if (s == HID * NLAB)        { W2 = (const float*)p; }
        else if (s == NLAB)              { b2 = (const float*)p; }
    }
    float* out = (float*)d_out;

    // CSR build (counting sort by row; feat rows then edge rows)
    k_zero<<<(N_SEG + 255) / 256, 256>>>();
    k_hist_f<<<(nnz + 255) / 256, 256>>>(fi, nnz);
    k_hist_e<<<(ne + 255) / 256, 256>>>(ei, ne);
    k_scan1<<<NBLK, 1024>>>();
    k_scan2<<<1, 256>>>();
    k_scan3<<<(N_SEG + 255) / 256, 256>>>();
    k_scat_f<<<(nnz + 255) / 256, 256>>>(fi, fv, nnz);
    k_scat_e<<<(ne + 255) / 256, 256>>>(ei, ew, ne, nnz);

    // GCN forward (gather-only, no atomics)
    k_feat_csr<<<(N_NODES + 15) / 16, 256>>>(W1, b1);
    k_edge64_csr<<<(N_NODES + 15) / 16, 256>>>(nnz);
    k_dense<<<(N_NODES + 255) / 256, 256>>>(W2, b2);
    k_edge40_csr<<<(N_NODES + 15) / 16, 256>>>(out, nnz);
    k_lsm<<<(N_NODES * 32 + 255) / 256, 256>>>(out);
}

// round 9
// speedup vs baseline: 2.1144x; 1.1088x over previous
#include <cuda_runtime.h>
#include <math.h>

#define N_NODES 100000
#define N_FEATS 2048
#define HID 64
#define NLAB 40
#define N_SEG (2 * N_NODES)          // feat rows [0,100K) + edge rows [100K,200K)
#define MAX_NNZ 2500000
#define MAX_NE  1700000
#define NBLK 196                     // ceil(N_SEG / 1024)

// ---- scratch (static: no allocations allowed) ----
__device__ __align__(16) float g_h1[N_NODES * HID];
__device__ __align__(16) float g_h2[N_NODES * HID];   // relu'ed after edge SpMM
__device__ __align__(16) float g_z1[N_NODES * NLAB];
__device__ int  g_cnt[N_SEG];
__device__ int  g_off[N_SEG];
__device__ int  g_bsum[256];
__device__ int  g_start[N_SEG];
__device__ int  g_cursor[N_SEG];
__device__ __align__(8) int2 g_fbuf[MAX_NNZ];         // (col, val bits) grouped by row
__device__ __align__(8) int2 g_ebuf[MAX_NE];          // (col, w bits) grouped by row

__device__ __forceinline__ int clamp_i(int i, int n) {
    i = i < 0 ? 0 : i;
    return i >= n ? n - 1 : i;
}

// token-capture-proof FMA accumulate (was a macro; broke on member '.w')
__device__ __forceinline__ void acc4(float4& a, float s, const float4& v) {
    a.x += s * v.x; a.y += s * v.y; a.z += s * v.z; a.w += s * v.w;
}

// ---------------- CSR build ----------------
__global__ void k_zero() {
    int i = blockIdx.x * blockDim.x + threadIdx.x;
    if (i < N_SEG) g_cnt[i] = 0;
}

// merged histogram: features then edges
__global__ void k_hist(const int* __restrict__ fi, int nnz,
                       const int* __restrict__ ei, int ne) {
    int e = blockIdx.x * blockDim.x + threadIdx.x;
    if (e < nnz) {
        atomicAdd(&g_cnt[clamp_i(__ldg(&fi[e]), N_NODES)], 1);
    } else if (e < nnz + ne) {
        int t = e - nnz;
        atomicAdd(&g_cnt[N_NODES + clamp_i(__ldg(&ei[t]), N_NODES)], 1);
    }
}

__global__ __launch_bounds__(1024) void k_scan1() {
    __shared__ int s[2][1024];
    int tid = threadIdx.x;
    int i = blockIdx.x * 1024 + tid;
    s[0][tid] = (i < N_SEG) ? g_cnt[i] : 0;
    __syncthreads();
    int cur = 0;
#pragma unroll
    for (int d = 1; d < 1024; d <<= 1) {
        int v = s[cur][tid];
        if (tid >= d) v += s[cur][tid - d];
        s[cur ^ 1][tid] = v;
        __syncthreads();
        cur ^= 1;
    }
    if (i < N_SEG) g_off[i] = s[cur][tid];
    if (tid == 1023) g_bsum[blockIdx.x] = s[cur][1023];
}

// merged: scan block sums (redundantly per block, cheap) + emit start/cursor
__global__ __launch_bounds__(256) void k_scan23() {
    __shared__ int s[2][256];
    int t = threadIdx.x;
    s[0][t] = (t < NBLK) ? g_bsum[t] : 0;
    __syncthreads();
    int cur = 0;
#pragma unroll
    for (int d = 1; d < 256; d <<= 1) {
        int v = s[cur][t];
        if (t >= d) v += s[cur][t - d];
        s[cur ^ 1][t] = v;
        __syncthreads();
        cur ^= 1;
    }
    __syncthreads();
    int i = blockIdx.x * blockDim.x + threadIdx.x;
    if (i >= N_SEG) return;
    int b = i >> 10;
    int base = b ? s[cur][b - 1] : 0;
    int st = g_off[i] + base - g_cnt[i];     // exclusive start
    g_start[i] = st;
    g_cursor[i] = st;
}

// merged scatter: features then edges
__global__ void k_scat(const int* __restrict__ fi, const float* __restrict__ fv, int nnz,
                       const int* __restrict__ ei, const float* __restrict__ ew, int ne) {
    int e = blockIdx.x * blockDim.x + threadIdx.x;
    if (e < nnz) {
        int row = clamp_i(__ldg(&fi[e]), N_NODES);
        int col = clamp_i(__ldg(&fi[nnz + e]), N_FEATS);
        float v = __ldg(&fv[e]);
        int pos = atomicAdd(&g_cursor[row], 1);
        g_fbuf[pos] = make_int2(col, __float_as_int(v));
    } else if (e < nnz + ne) {
        int t = e - nnz;
        int row = clamp_i(__ldg(&ei[t]), N_NODES);
        int col = clamp_i(__ldg(&ei[ne + t]), N_NODES);
        float wv = __ldg(&ew[t]);
        int pos = atomicAdd(&g_cursor[N_NODES + row], 1) - nnz;
        g_ebuf[pos] = make_int2(col, __float_as_int(wv));
    }
}

// ---------------- gather-only SpMMs (16 lanes per row, float4 per lane) ----------------
// h1[row] = b1 + sum_i val_i * W1[col_i, :]
__global__ __launch_bounds__(256) void k_feat_csr(const float* __restrict__ W1,
                                                  const float* __restrict__ b1) {
    int tid = threadIdx.x;
    int row = blockIdx.x * 16 + (tid >> 4);
    int q = tid & 15;
    if (row >= N_NODES) return;
    int s = g_start[row];
    int n = g_cnt[row];
    float4 acc = __ldg((const float4*)b1 + q);
    int i = 0;
    for (; i + 4 <= n; i += 4) {
        int2 p0 = __ldg(&g_fbuf[s + i]);
        int2 p1 = __ldg(&g_fbuf[s + i + 1]);
        int2 p2 = __ldg(&g_fbuf[s + i + 2]);
        int2 p3 = __ldg(&g_fbuf[s + i + 3]);
        float4 w0 = __ldg((const float4*)(W1 + (size_t)p0.x * HID) + q);
        float4 w1 = __ldg((const float4*)(W1 + (size_t)p1.x * HID) + q);
        float4 w2 = __ldg((const float4*)(W1 + (size_t)p2.x * HID) + q);
        float4 w3 = __ldg((const float4*)(W1 + (size_t)p3.x * HID) + q);
        acc4(acc, __int_as_float(p0.y), w0);
        acc4(acc, __int_as_float(p1.y), w1);
        acc4(acc, __int_as_float(p2.y), w2);
        acc4(acc, __int_as_float(p3.y), w3);
    }
    for (; i < n; i++) {
        int2 p = __ldg(&g_fbuf[s + i]);
        float4 wv = __ldg((const float4*)(W1 + (size_t)p.x * HID) + q);
        acc4(acc, __int_as_float(p.y), wv);
    }
    *((float4*)(g_h1 + (size_t)row * HID) + q) = acc;
}

// h2[row] = relu( sum_i w_i * h1[col_i] )
__global__ __launch_bounds__(256) void k_edge64_csr(int nnz) {
    int tid = threadIdx.x;
    int row = blockIdx.x * 16 + (tid >> 4);
    int q = tid & 15;
    if (row >= N_NODES) return;
    int s = g_start[N_NODES + row] - nnz;
    int n = g_cnt[N_NODES + row];
    float4 acc = make_float4(0.f, 0.f, 0.f, 0.f);
    int i = 0;
    for (; i + 4 <= n; i += 4) {
        int2 p0 = __ldg(&g_ebuf[s + i]);
        int2 p1 = __ldg(&g_ebuf[s + i + 1]);
        int2 p2 = __ldg(&g_ebuf[s + i + 2]);
        int2 p3 = __ldg(&g_ebuf[s + i + 3]);
        float4 h0 = __ldg((const float4*)(g_h1 + (size_t)p0.x * HID) + q);
        float4 h1 = __ldg((const float4*)(g_h1 + (size_t)p1.x * HID) + q);
        float4 h2 = __ldg((const float4*)(g_h1 + (size_t)p2.x * HID) + q);
        float4 h3 = __ldg((const float4*)(g_h1 + (size_t)p3.x * HID) + q);
        acc4(acc, __int_as_float(p0.y), h0);
        acc4(acc, __int_as_float(p1.y), h1);
        acc4(acc, __int_as_float(p2.y), h2);
        acc4(acc, __int_as_float(p3.y), h3);
    }
    for (; i < n; i++) {
        int2 p = __ldg(&g_ebuf[s + i]);
        float4 hv = __ldg((const float4*)(g_h1 + (size_t)p.x * HID) + q);
        acc4(acc, __int_as_float(p.y), hv);
    }
    acc.x = fmaxf(acc.x, 0.f); acc.y = fmaxf(acc.y, 0.f);
    acc.z = fmaxf(acc.z, 0.f); acc.w = fmaxf(acc.w, 0.f);
    *((float4*)(g_h2 + (size_t)row * HID) + q) = acc;
}

// ---------------- dense: z1 = h2 @ W2 + b2 ----------------
#define PADK 68
__global__ __launch_bounds__(256) void k_dense(const float* __restrict__ W2,
                                               const float* __restrict__ b2) {
    __shared__ float sW2t[NLAB * PADK];   // [j][k]
    __shared__ float sb2[NLAB];
    int tid = threadIdx.x;
    for (int i = tid; i < HID * NLAB; i += 256) {
        int k = i / NLAB, j = i - k * NLAB;
        sW2t[j * PADK + k] = W2[i];
    }
    if (tid < NLAB) sb2[tid] = b2[tid];
    __syncthreads();

    int j0 = (tid & 3) * 10;
    int n0 = (blockIdx.x * 64 + (tid >> 2)) * 4;

    float acc[4][10];
#pragma unroll
    for (int nn = 0; nn < 4; nn++)
#pragma unroll
        for (int j = 0; j < 10; j++) acc[nn][j] = sb2[j0 + j];

#pragma unroll
    for (int k4 = 0; k4 < HID; k4 += 4) {
        float4 h[4];
#pragma unroll
        for (int nn = 0; nn < 4; nn++) {
            int nd = n0 + nn;
            h[nn] = (nd < N_NODES) ? __ldg((const float4*)(g_h2 + (size_t)nd * HID + k4))
                                   : make_float4(0.f, 0.f, 0.f, 0.f);
        }
#pragma unroll
        for (int j = 0; j < 10; j++) {
            float4 wv = *(const float4*)&sW2t[(j0 + j) * PADK + k4];
#pragma unroll
            for (int nn = 0; nn < 4; nn++)
                acc[nn][j] += h[nn].x * wv.x + h[nn].y * wv.y + h[nn].z * wv.z + h[nn].w * wv.w;
        }
    }
#pragma unroll
    for (int nn = 0; nn < 4; nn++) {
        int nd = n0 + nn;
        if (nd >= N_NODES) break;
        float* zp = g_z1 + (size_t)nd * NLAB + j0;
#pragma unroll
        for (int j = 0; j < 10; j += 2)
            *(float2*)(zp + j) = make_float2(acc[nn][j], acc[nn][j + 1]);
    }
}

// ---------------- final propagate + fused log-softmax ----------------
// out[row] = log_softmax( sum_i w_i * z1[col_i] ); 16 lanes/row, lanes 0..9 active.
__global__ __launch_bounds__(256) void k_edge40_lsm(float* __restrict__ out, int nnz) {
    int tid = threadIdx.x;
    int row = blockIdx.x * 16 + (tid >> 4);
    int q = tid & 15;
    if (row >= N_NODES) return;
    int s = g_start[N_NODES + row] - nnz;
    int n = g_cnt[N_NODES + row];
    bool act = (q < 10);
    float4 acc = make_float4(0.f, 0.f, 0.f, 0.f);
    int i = 0;
    for (; i + 4 <= n; i += 4) {
        int2 p0 = __ldg(&g_ebuf[s + i]);
        int2 p1 = __ldg(&g_ebuf[s + i + 1]);
        int2 p2 = __ldg(&g_ebuf[s + i + 2]);
        int2 p3 = __ldg(&g_ebuf[s + i + 3]);
        if (act) {
            float4 z0 = __ldg((const float4*)(g_z1 + (size_t)p0.x * NLAB) + q);
            float4 zz1 = __ldg((const float4*)(g_z1 + (size_t)p1.x * NLAB) + q);
            float4 zz2 = __ldg((const float4*)(g_z1 + (size_t)p2.x * NLAB) + q);
            float4 zz3 = __ldg((const float4*)(g_z1 + (size_t)p3.x * NLAB) + q);
            acc4(acc, __int_as_float(p0.y), z0);
            acc4(acc, __int_as_float(p1.y), zz1);
            acc4(acc, __int_as_float(p2.y), zz2);
            acc4(acc, __int_as_float(p3.y), zz3);
        }
    }
    for (; i < n; i++) {
        int2 p = __ldg(&g_ebuf[s + i]);
        if (act) {
            float4 zv = __ldg((const float4*)(g_z1 + (size_t)p.x * NLAB) + q);
            acc4(acc, __int_as_float(p.y), zv);
        }
    }
    // log-softmax across the 16-lane group (lanes 0..9 hold the 40 values)
    float m = act ? fmaxf(fmaxf(acc.x, acc.y), fmaxf(acc.z, acc.w)) : -1e30f;
#pragma unroll
    for (int o = 1; o < 16; o <<= 1) m = fmaxf(m, __shfl_xor_sync(0xFFFFFFFFu, m, o, 16));
    float es = act ? (expf(acc.x - m) + expf(acc.y - m) + expf(acc.z - m) + expf(acc.w - m)) : 0.f;
#pragma unroll
    for (int o = 1; o < 16; o <<= 1) es += __shfl_xor_sync(0xFFFFFFFFu, es, o, 16);
    float l = m + logf(es);
    if (act) {
        *((float4*)(out + (size_t)row * NLAB) + q) =
            make_float4(acc.x - l, acc.y - l, acc.z - l, acc.w - l);
    }
}

extern "C" void kernel_launch(void* const* d_in, const int* in_sizes, int n_in,
                              void* d_out, int out_size) {
    // Bind inputs by element count (pairwise distinct); indices are int32.
    const int* fi = 0; const float* fv = 0;
    const int* ei = 0; const float* ew = 0;
    const float *W1 = 0, *b1 = 0, *W2 = 0, *b2 = 0;
    int nnz = 0, ne = 0;
    for (int i = 0; i < n_in; i++) {
        int s = in_sizes[i];
        const void* p = d_in[i];
        if (s == 2 * MAX_NNZ)            { fi = (const int*)p; }
        else if (s == MAX_NNZ)           { fv = (const float*)p; nnz = s; }
        else if (s == 2 * MAX_NE)        { ei = (const int*)p; }
        else if (s == MAX_NE)            { ew = (const float*)p; ne = s; }
        else if (s == N_FEATS * HID)     { W1 = (const float*)p; }
        else if (s == HID)               { b1 = (const float*)p; }
        else if (s == HID * NLAB)        { W2 = (const float*)p; }
        else if (s == NLAB)              { b2 = (const float*)p; }
    }
    float* out = (float*)d_out;
    int tot = nnz + ne;

    // CSR build (counting sort by row; feat rows then edge rows)
    k_zero<<<(N_SEG + 255) / 256, 256>>>();
    k_hist<<<(tot + 255) / 256, 256>>>(fi, nnz, ei, ne);
    k_scan1<<<NBLK, 1024>>>();
    k_scan23<<<(N_SEG + 255) / 256, 256>>>();
    k_scat<<<(tot + 255) / 256, 256>>>(fi, fv, nnz, ei, ew, ne);

    // GCN forward (gather-only, no atomics)
    k_feat_csr<<<(N_NODES + 15) / 16, 256>>>(W1, b1);
    k_edge64_csr<<<(N_NODES + 15) / 16, 256>>>(nnz);
    k_dense<<<(N_NODES + 255) / 256, 256>>>(W2, b2);
    k_edge40_lsm<<<(N_NODES + 15) / 16, 256>>>(out, nnz);
}

// round 10
// speedup vs baseline: 2.4070x; 1.1383x over previous
#include <cuda_runtime.h>
#include <cuda_fp16.h>
#include <math.h>

#define N_NODES 100000
#define N_FEATS 2048
#define HID 64
#define NLAB 40
#define N_SEG (2 * N_NODES)          // feat rows [0,100K) + edge rows [100K,200K)
#define MAX_NNZ 2500000
#define MAX_NE  1700000
#define NBLK 196                     // ceil(N_SEG / 1024)

// ---- scratch (static: no allocations allowed) ----
__device__ __align__(16) __half2 g_W1h[N_FEATS * HID / 2];   // fp16 copy of W1 (256 KB)
__device__ __align__(16) __half2 g_h1h[N_NODES * HID / 2];   // h1 in fp16 (12.8 MB)
__device__ __align__(16) float   g_h2[N_NODES * HID];        // relu'ed, fp32 (25.6 MB)
__device__ __align__(16) float   g_z1[N_NODES * NLAB];
__device__ int  g_cnt[N_SEG];
__device__ int  g_off[N_SEG];
__device__ int  g_bsum[256];
__device__ int  g_start[N_SEG];
__device__ int  g_cursor[N_SEG];
__device__ __align__(8) int2 g_fbuf[MAX_NNZ];         // (col, val bits) grouped by row
__device__ __align__(8) int2 g_ebuf[MAX_NE];          // (col, w bits) grouped by row

__device__ __forceinline__ int clamp_i(int i, int n) {
    i = i < 0 ? 0 : i;
    return i >= n ? n - 1 : i;
}

__device__ __forceinline__ void acc4(float4& a, float s, const float4& v) {
    a.x += s * v.x; a.y += s * v.y; a.z += s * v.z; a.w += s * v.w;
}

// unpack 4 halves (as uint2) -> float4
__device__ __forceinline__ float4 h4_to_f4(uint2 u) {
    __half2 a = *(__half2*)&u.x;
    __half2 b = *(__half2*)&u.y;
    float2 fa = __half22float2(a);
    float2 fb = __half22float2(b);
    return make_float4(fa.x, fa.y, fb.x, fb.y);
}

// ---------------- CSR build (+ W1 fp16 conversion folded in) ----------------
__global__ void k_zero(const float* __restrict__ W1) {
    int i = blockIdx.x * blockDim.x + threadIdx.x;
    if (i < N_SEG) g_cnt[i] = 0;
    if (i < N_FEATS * HID / 2) {
        float2 f = __ldg((const float2*)W1 + i);
        g_W1h[i] = __floats2half2_rn(f.x, f.y);
    }
}

// merged histogram: features then edges
__global__ void k_hist(const int* __restrict__ fi, int nnz,
                       const int* __restrict__ ei, int ne) {
    int e = blockIdx.x * blockDim.x + threadIdx.x;
    if (e < nnz) {
        atomicAdd(&g_cnt[clamp_i(__ldg(&fi[e]), N_NODES)], 1);
    } else if (e < nnz + ne) {
        int t = e - nnz;
        atomicAdd(&g_cnt[N_NODES + clamp_i(__ldg(&ei[t]), N_NODES)], 1);
    }
}

__global__ __launch_bounds__(1024) void k_scan1() {
    __shared__ int s[2][1024];
    int tid = threadIdx.x;
    int i = blockIdx.x * 1024 + tid;
    s[0][tid] = (i < N_SEG) ? g_cnt[i] : 0;
    __syncthreads();
    int cur = 0;
#pragma unroll
    for (int d = 1; d < 1024; d <<= 1) {
        int v = s[cur][tid];
        if (tid >= d) v += s[cur][tid - d];
        s[cur ^ 1][tid] = v;
        __syncthreads();
        cur ^= 1;
    }
    if (i < N_SEG) g_off[i] = s[cur][tid];
    if (tid == 1023) g_bsum[blockIdx.x] = s[cur][1023];
}

// merged: scan block sums (redundantly per block, cheap) + emit start/cursor
__global__ __launch_bounds__(256) void k_scan23() {
    __shared__ int s[2][256];
    int t = threadIdx.x;
    s[0][t] = (t < NBLK) ? g_bsum[t] : 0;
    __syncthreads();
    int cur = 0;
#pragma unroll
    for (int d = 1; d < 256; d <<= 1) {
        int v = s[cur][t];
        if (t >= d) v += s[cur][t - d];
        s[cur ^ 1][t] = v;
        __syncthreads();
        cur ^= 1;
    }
    __syncthreads();
    int i = blockIdx.x * blockDim.x + threadIdx.x;
    if (i >= N_SEG) return;
    int b = i >> 10;
    int base = b ? s[cur][b - 1] : 0;
    int st = g_off[i] + base - g_cnt[i];     // exclusive start
    g_start[i] = st;
    g_cursor[i] = st;
}

// merged scatter: features then edges
__global__ void k_scat(const int* __restrict__ fi, const float* __restrict__ fv, int nnz,
                       const int* __restrict__ ei, const float* __restrict__ ew, int ne) {
    int e = blockIdx.x * blockDim.x + threadIdx.x;
    if (e < nnz) {
        int row = clamp_i(__ldg(&fi[e]), N_NODES);
        int col = clamp_i(__ldg(&fi[nnz + e]), N_FEATS);
        float v = __ldg(&fv[e]);
        int pos = atomicAdd(&g_cursor[row], 1);
        g_fbuf[pos] = make_int2(col, __float_as_int(v));
    } else if (e < nnz + ne) {
        int t = e - nnz;
        int row = clamp_i(__ldg(&ei[t]), N_NODES);
        int col = clamp_i(__ldg(&ei[ne + t]), N_NODES);
        float wv = __ldg(&ew[t]);
        int pos = atomicAdd(&g_cursor[N_NODES + row], 1) - nnz;
        g_ebuf[pos] = make_int2(col, __float_as_int(wv));
    }
}

// ---------------- gather-only SpMMs (16 lanes per row) ----------------
// h1[row] = b1 + sum_i val_i * W1[col_i, :]; W1 fp16-gather, fp32 accum, fp16 store.
__global__ __launch_bounds__(256) void k_feat_csr(const float* __restrict__ b1) {
    int tid = threadIdx.x;
    int row = blockIdx.x * 16 + (tid >> 4);
    int q = tid & 15;
    if (row >= N_NODES) return;
    int s = g_start[row];
    int n = g_cnt[row];
    float4 acc = __ldg((const float4*)b1 + q);
    const uint2* W = (const uint2*)g_W1h;     // 16 uint2 per W1 row
    int i = 0;
    for (; i + 4 <= n; i += 4) {
        int2 p0 = __ldg(&g_fbuf[s + i]);
        int2 p1 = __ldg(&g_fbuf[s + i + 1]);
        int2 p2 = __ldg(&g_fbuf[s + i + 2]);
        int2 p3 = __ldg(&g_fbuf[s + i + 3]);
        uint2 u0 = __ldg(W + (size_t)p0.x * 16 + q);
        uint2 u1 = __ldg(W + (size_t)p1.x * 16 + q);
        uint2 u2 = __ldg(W + (size_t)p2.x * 16 + q);
        uint2 u3 = __ldg(W + (size_t)p3.x * 16 + q);
        acc4(acc, __int_as_float(p0.y), h4_to_f4(u0));
        acc4(acc, __int_as_float(p1.y), h4_to_f4(u1));
        acc4(acc, __int_as_float(p2.y), h4_to_f4(u2));
        acc4(acc, __int_as_float(p3.y), h4_to_f4(u3));
    }
    for (; i < n; i++) {
        int2 p = __ldg(&g_fbuf[s + i]);
        uint2 u = __ldg(W + (size_t)p.x * 16 + q);
        acc4(acc, __int_as_float(p.y), h4_to_f4(u));
    }
    __half2 ha = __floats2half2_rn(acc.x, acc.y);
    __half2 hb = __floats2half2_rn(acc.z, acc.w);
    uint2 o;
    o.x = *(unsigned*)&ha; o.y = *(unsigned*)&hb;
    ((uint2*)g_h1h)[(size_t)row * 16 + q] = o;
}

// h2[row] = relu( sum_i w_i * h1[col_i] ); h1 fp16-gather, fp32 accum/store.
__global__ __launch_bounds__(256) void k_edge64_csr(int nnz) {
    int tid = threadIdx.x;
    int row = blockIdx.x * 16 + (tid >> 4);
    int q = tid & 15;
    if (row >= N_NODES) return;
    int s = g_start[N_NODES + row] - nnz;
    int n = g_cnt[N_NODES + row];
    const uint2* H = (const uint2*)g_h1h;
    float4 acc = make_float4(0.f, 0.f, 0.f, 0.f);
    int i = 0;
    for (; i + 4 <= n; i += 4) {
        int2 p0 = __ldg(&g_ebuf[s + i]);
        int2 p1 = __ldg(&g_ebuf[s + i + 1]);
        int2 p2 = __ldg(&g_ebuf[s + i + 2]);
        int2 p3 = __ldg(&g_ebuf[s + i + 3]);
        uint2 u0 = __ldg(H + (size_t)p0.x * 16 + q);
        uint2 u1 = __ldg(H + (size_t)p1.x * 16 + q);
        uint2 u2 = __ldg(H + (size_t)p2.x * 16 + q);
        uint2 u3 = __ldg(H + (size_t)p3.x * 16 + q);
        acc4(acc, __int_as_float(p0.y), h4_to_f4(u0));
        acc4(acc, __int_as_float(p1.y), h4_to_f4(u1));
        acc4(acc, __int_as_float(p2.y), h4_to_f4(u2));
        acc4(acc, __int_as_float(p3.y), h4_to_f4(u3));
    }
    for (; i < n; i++) {
        int2 p = __ldg(&g_ebuf[s + i]);
        uint2 u = __ldg(H + (size_t)p.x * 16 + q);
        acc4(acc, __int_as_float(p.y), h4_to_f4(u));
    }
    acc.x = fmaxf(acc.x, 0.f); acc.y = fmaxf(acc.y, 0.f);
    acc.z = fmaxf(acc.z, 0.f); acc.w = fmaxf(acc.w, 0.f);
    *((float4*)(g_h2 + (size_t)row * HID) + q) = acc;
}

// ---------------- dense: z1 = h2 @ W2 + b2 ----------------
#define PADK 68
__global__ __launch_bounds__(256) void k_dense(const float* __restrict__ W2,
                                               const float* __restrict__ b2) {
    __shared__ float sW2t[NLAB * PADK];   // [j][k]
    __shared__ float sb2[NLAB];
    int tid = threadIdx.x;
    for (int i = tid; i < HID * NLAB; i += 256) {
        int k = i / NLAB, j = i - k * NLAB;
        sW2t[j * PADK + k] = W2[i];
    }
    if (tid < NLAB) sb2[tid] = b2[tid];
    __syncthreads();

    int j0 = (tid & 3) * 10;
    int n0 = (blockIdx.x * 64 + (tid >> 2)) * 4;

    float acc[4][10];
#pragma unroll
    for (int nn = 0; nn < 4; nn++)
#pragma unroll
        for (int j = 0; j < 10; j++) acc[nn][j] = sb2[j0 + j];

#pragma unroll
    for (int k4 = 0; k4 < HID; k4 += 4) {
        float4 h[4];
#pragma unroll
        for (int nn = 0; nn < 4; nn++) {
            int nd = n0 + nn;
            h[nn] = (nd < N_NODES) ? __ldg((const float4*)(g_h2 + (size_t)nd * HID + k4))
                                   : make_float4(0.f, 0.f, 0.f, 0.f);
        }
#pragma unroll
        for (int j = 0; j < 10; j++) {
            float4 wv = *(const float4*)&sW2t[(j0 + j) * PADK + k4];
#pragma unroll
            for (int nn = 0; nn < 4; nn++)
                acc[nn][j] += h[nn].x * wv.x + h[nn].y * wv.y + h[nn].z * wv.z + h[nn].w * wv.w;
        }
    }
#pragma unroll
    for (int nn = 0; nn < 4; nn++) {
        int nd = n0 + nn;
        if (nd >= N_NODES) break;
        float* zp = g_z1 + (size_t)nd * NLAB + j0;
#pragma unroll
        for (int j = 0; j < 10; j += 2)
            *(float2*)(zp + j) = make_float2(acc[nn][j], acc[nn][j + 1]);
    }
}

// ---------------- final propagate + fused log-softmax ----------------
__global__ __launch_bounds__(256) void k_edge40_lsm(float* __restrict__ out, int nnz) {
    int tid = threadIdx.x;
    int row = blockIdx.x * 16 + (tid >> 4);
    int q = tid & 15;
    if (row >= N_NODES) return;
    int s = g_start[N_NODES + row] - nnz;
    int n = g_cnt[N_NODES + row];
    bool act = (q < 10);
    float4 acc = make_float4(0.f, 0.f, 0.f, 0.f);
    int i = 0;
    for (; i + 4 <= n; i += 4) {
        int2 p0 = __ldg(&g_ebuf[s + i]);
        int2 p1 = __ldg(&g_ebuf[s + i + 1]);
        int2 p2 = __ldg(&g_ebuf[s + i + 2]);
        int2 p3 = __ldg(&g_ebuf[s + i + 3]);
        if (act) {
            float4 z0 = __ldg((const float4*)(g_z1 + (size_t)p0.x * NLAB) + q);
            float4 zz1 = __ldg((const float4*)(g_z1 + (size_t)p1.x * NLAB) + q);
            float4 zz2 = __ldg((const float4*)(g_z1 + (size_t)p2.x * NLAB) + q);
            float4 zz3 = __ldg((const float4*)(g_z1 + (size_t)p3.x * NLAB) + q);
            acc4(acc, __int_as_float(p0.y), z0);
            acc4(acc, __int_as_float(p1.y), zz1);
            acc4(acc, __int_as_float(p2.y), zz2);
            acc4(acc, __int_as_float(p3.y), zz3);
        }
    }
    for (; i < n; i++) {
        int2 p = __ldg(&g_ebuf[s + i]);
        if (act) {
            float4 zv = __ldg((const float4*)(g_z1 + (size_t)p.x * NLAB) + q);
            acc4(acc, __int_as_float(p.y), zv);
        }
    }
    float m = act ? fmaxf(fmaxf(acc.x, acc.y), fmaxf(acc.z, acc.w)) : -1e30f;
#pragma unroll
    for (int o = 1; o < 16; o <<= 1) m = fmaxf(m, __shfl_xor_sync(0xFFFFFFFFu, m, o, 16));
    float es = act ? (expf(acc.x - m) + expf(acc.y - m) + expf(acc.z - m) + expf(acc.w - m)) : 0.f;
#pragma unroll
    for (int o = 1; o < 16; o <<= 1) es += __shfl_xor_sync(0xFFFFFFFFu, es, o, 16);
    float l = m + logf(es);
    if (act) {
        *((float4*)(out + (size_t)row * NLAB) + q) =
            make_float4(acc.x - l, acc.y - l, acc.z - l, acc.w - l);
    }
}

extern "C" void kernel_launch(void* const* d_in, const int* in_sizes, int n_in,
                              void* d_out, int out_size) {
    // Bind inputs by element count (pairwise distinct); indices are int32.
    const int* fi = 0; const float* fv = 0;
    const int* ei = 0; const float* ew = 0;
    const float *W1 = 0, *b1 = 0, *W2 = 0, *b2 = 0;
    int nnz = 0, ne = 0;
    for (int i = 0; i < n_in; i++) {
        int s = in_sizes[i];
        const void* p = d_in[i];
        if (s == 2 * MAX_NNZ)            { fi = (const int*)p; }
        else if (s == MAX_NNZ)           { fv = (const float*)p; nnz = s; }
        else if (s == 2 * MAX_NE)        { ei = (const int*)p; }
        else if (s == MAX_NE)            { ew = (const float*)p; ne = s; }
        else if (s == N_FEATS * HID)     { W1 = (const float*)p; }
        else if (s == HID)               { b1 = (const float*)p; }
        else if (s == HID * NLAB)        { W2 = (const float*)p; }
        else if (s == NLAB)              { b2 = (const float*)p; }
    }
    float* out = (float*)d_out;
    int tot = nnz + ne;

    // CSR build (counting sort by row; feat rows then edge rows) + W1 fp16 convert
    k_zero<<<(N_SEG + 255) / 256, 256>>>(W1);
    k_hist<<<(tot + 255) / 256, 256>>>(fi, nnz, ei, ne);
    k_scan1<<<NBLK, 1024>>>();
    k_scan23<<<(N_SEG + 255) / 256, 256>>>();
    k_scat<<<(tot + 255) / 256, 256>>>(fi, fv, nnz, ei, ew, ne);

    // GCN forward (gather-only, no atomics)
    k_feat_csr<<<(N_NODES + 15) / 16, 256>>>(b1);
    k_edge64_csr<<<(N_NODES + 15) / 16, 256>>>(nnz);
    k_dense<<<(N_NODES + 255) / 256, 256>>>(W2, b2);
    k_edge40_lsm<<<(N_NODES + 15) / 16, 256>>>(out, nnz);
}

// round 11
// speedup vs baseline: 2.5846x; 1.0738x over previous
#include <cuda_runtime.h>
#include <cuda_fp16.h>
#include <math.h>

#define N_NODES 100000
#define N_FEATS 2048
#define HID 64
#define NLAB 40
#define N_SEG (2 * N_NODES)          // feat rows [0,100K) + edge rows [100K,200K)
#define MAX_NNZ 2500000
#define MAX_NE  1700000
#define NBLK 196                     // ceil(N_SEG / 1024)

// ---- scratch (static: no allocations allowed) ----
__device__ __align__(16) __half2 g_W1h[N_FEATS * HID / 2];   // fp16 W1 (256 KB)
__device__ __align__(16) __half2 g_h1h[N_NODES * HID / 2];   // h1 fp16 (12.8 MB)
__device__ __align__(16) __half2 g_h2h[N_NODES * HID / 2];   // h2 fp16, relu'ed (12.8 MB)
__device__ __align__(16) __half2 g_z1h[N_NODES * NLAB / 2];  // z1 fp16 (8 MB)
__device__ int  g_cnt[N_SEG];
__device__ int  g_off[N_SEG];
__device__ int  g_bsum[256];
__device__ int  g_start[N_SEG];
__device__ int  g_cursor[N_SEG];
__device__ unsigned g_fbuf[MAX_NNZ];                  // (col<<16)|fp16(val), by row
__device__ __align__(8) int2 g_ebuf[MAX_NE];          // (col, w bits) grouped by row

__device__ __forceinline__ int clamp_i(int i, int n) {
    i = i < 0 ? 0 : i;
    return i >= n ? n - 1 : i;
}

__device__ __forceinline__ void acc4(float4& a, float s, const float4& v) {
    a.x += s * v.x; a.y += s * v.y; a.z += s * v.z; a.w += s * v.w;
}

// unpack 4 halves (as uint2) -> float4
__device__ __forceinline__ float4 h4_to_f4(uint2 u) {
    __half2 a = *(__half2*)&u.x;
    __half2 b = *(__half2*)&u.y;
    float2 fa = __half22float2(a);
    float2 fb = __half22float2(b);
    return make_float4(fa.x, fa.y, fb.x, fb.y);
}

__device__ __forceinline__ uint2 f4_to_h4(float4 f) {
    __half2 a = __floats2half2_rn(f.x, f.y);
    __half2 b = __floats2half2_rn(f.z, f.w);
    uint2 u;
    u.x = *(unsigned*)&a; u.y = *(unsigned*)&b;
    return u;
}

// ---------------- CSR build (+ W1 fp16 conversion folded in) ----------------
__global__ void k_zero(const float* __restrict__ W1) {
    int i = blockIdx.x * blockDim.x + threadIdx.x;
    if (i < N_SEG) g_cnt[i] = 0;
    if (i < N_FEATS * HID / 2) {
        float2 f = __ldg((const float2*)W1 + i);
        g_W1h[i] = __floats2half2_rn(f.x, f.y);
    }
}

__global__ void k_hist(const int* __restrict__ fi, int nnz,
                       const int* __restrict__ ei, int ne) {
    int e = blockIdx.x * blockDim.x + threadIdx.x;
    if (e < nnz) {
        atomicAdd(&g_cnt[clamp_i(__ldg(&fi[e]), N_NODES)], 1);
    } else if (e < nnz + ne) {
        int t = e - nnz;
        atomicAdd(&g_cnt[N_NODES + clamp_i(__ldg(&ei[t]), N_NODES)], 1);
    }
}

__global__ __launch_bounds__(1024) void k_scan1() {
    __shared__ int s[2][1024];
    int tid = threadIdx.x;
    int i = blockIdx.x * 1024 + tid;
    s[0][tid] = (i < N_SEG) ? g_cnt[i] : 0;
    __syncthreads();
    int cur = 0;
#pragma unroll
    for (int d = 1; d < 1024; d <<= 1) {
        int v = s[cur][tid];
        if (tid >= d) v += s[cur][tid - d];
        s[cur ^ 1][tid] = v;
        __syncthreads();
        cur ^= 1;
    }
    if (i < N_SEG) g_off[i] = s[cur][tid];
    if (tid == 1023) g_bsum[blockIdx.x] = s[cur][1023];
}

__global__ __launch_bounds__(256) void k_scan23() {
    __shared__ int s[2][256];
    int t = threadIdx.x;
    s[0][t] = (t < NBLK) ? g_bsum[t] : 0;
    __syncthreads();
    int cur = 0;
#pragma unroll
    for (int d = 1; d < 256; d <<= 1) {
        int v = s[cur][t];
        if (t >= d) v += s[cur][t - d];
        s[cur ^ 1][t] = v;
        __syncthreads();
        cur ^= 1;
    }
    __syncthreads();
    int i = blockIdx.x * blockDim.x + threadIdx.x;
    if (i >= N_SEG) return;
    int b = i >> 10;
    int base = b ? s[cur][b - 1] : 0;
    int st = g_off[i] + base - g_cnt[i];     // exclusive start
    g_start[i] = st;
    g_cursor[i] = st;
}

// merged scatter: features (packed 4B) then edges (8B)
__global__ void k_scat(const int* __restrict__ fi, const float* __restrict__ fv, int nnz,
                       const int* __restrict__ ei, const float* __restrict__ ew, int ne) {
    int e = blockIdx.x * blockDim.x + threadIdx.x;
    if (e < nnz) {
        int row = clamp_i(__ldg(&fi[e]), N_NODES);
        int col = clamp_i(__ldg(&fi[nnz + e]), N_FEATS);
        __half hv = __float2half_rn(__ldg(&fv[e]));
        int pos = atomicAdd(&g_cursor[row], 1);
        g_fbuf[pos] = ((unsigned)col << 16) | (unsigned)*(unsigned short*)&hv;
    } else if (e < nnz + ne) {
        int t = e - nnz;
        int row = clamp_i(__ldg(&ei[t]), N_NODES);
        int col = clamp_i(__ldg(&ei[ne + t]), N_NODES);
        float wv = __ldg(&ew[t]);
        int pos = atomicAdd(&g_cursor[N_NODES + row], 1) - nnz;
        g_ebuf[pos] = make_int2(col, __float_as_int(wv));
    }
}

// ---------------- gather-only SpMMs (16 lanes per row) ----------------
__device__ __forceinline__ float fent_val(unsigned p) {
    unsigned short b = (unsigned short)(p & 0xFFFFu);
    return __half2float(*(__half*)&b);
}

// h1[row] = b1 + sum_i val_i * W1[col_i, :]; all gathers fp16, fp32 accum.
__global__ __launch_bounds__(256) void k_feat_csr(const float* __restrict__ b1) {
    int tid = threadIdx.x;
    int row = blockIdx.x * 16 + (tid >> 4);
    int q = tid & 15;
    if (row >= N_NODES) return;
    int s = g_start[row];
    int n = g_cnt[row];
    float4 acc = __ldg((const float4*)b1 + q);
    const uint2* W = (const uint2*)g_W1h;     // 16 uint2 per W1 row
    int i = 0;
    for (; i + 4 <= n; i += 4) {
        unsigned p0 = __ldg(&g_fbuf[s + i]);
        unsigned p1 = __ldg(&g_fbuf[s + i + 1]);
        unsigned p2 = __ldg(&g_fbuf[s + i + 2]);
        unsigned p3 = __ldg(&g_fbuf[s + i + 3]);
        uint2 u0 = __ldg(W + (size_t)(p0 >> 16) * 16 + q);
        uint2 u1 = __ldg(W + (size_t)(p1 >> 16) * 16 + q);
        uint2 u2 = __ldg(W + (size_t)(p2 >> 16) * 16 + q);
        uint2 u3 = __ldg(W + (size_t)(p3 >> 16) * 16 + q);
        acc4(acc, fent_val(p0), h4_to_f4(u0));
        acc4(acc, fent_val(p1), h4_to_f4(u1));
        acc4(acc, fent_val(p2), h4_to_f4(u2));
        acc4(acc, fent_val(p3), h4_to_f4(u3));
    }
    for (; i < n; i++) {
        unsigned p = __ldg(&g_fbuf[s + i]);
        uint2 u = __ldg(W + (size_t)(p >> 16) * 16 + q);
        acc4(acc, fent_val(p), h4_to_f4(u));
    }
    ((uint2*)g_h1h)[(size_t)row * 16 + q] = f4_to_h4(acc);
}

// h2[row] = relu( sum_i w_i * h1[col_i] ); fp16 gather + fp16 store, fp32 accum.
__global__ __launch_bounds__(256) void k_edge64_csr(int nnz) {
    int tid = threadIdx.x;
    int row = blockIdx.x * 16 + (tid >> 4);
    int q = tid & 15;
    if (row >= N_NODES) return;
    int s = g_start[N_NODES + row] - nnz;
    int n = g_cnt[N_NODES + row];
    const uint2* H = (const uint2*)g_h1h;
    float4 acc = make_float4(0.f, 0.f, 0.f, 0.f);
    int i = 0;
    for (; i + 4 <= n; i += 4) {
        int2 p0 = __ldg(&g_ebuf[s + i]);
        int2 p1 = __ldg(&g_ebuf[s + i + 1]);
        int2 p2 = __ldg(&g_ebuf[s + i + 2]);
        int2 p3 = __ldg(&g_ebuf[s + i + 3]);
        uint2 u0 = __ldg(H + (size_t)p0.x * 16 + q);
        uint2 u1 = __ldg(H + (size_t)p1.x * 16 + q);
        uint2 u2 = __ldg(H + (size_t)p2.x * 16 + q);
        uint2 u3 = __ldg(H + (size_t)p3.x * 16 + q);
        acc4(acc, __int_as_float(p0.y), h4_to_f4(u0));
        acc4(acc, __int_as_float(p1.y), h4_to_f4(u1));
        acc4(acc, __int_as_float(p2.y), h4_to_f4(u2));
        acc4(acc, __int_as_float(p3.y), h4_to_f4(u3));
    }
    for (; i < n; i++) {
        int2 p = __ldg(&g_ebuf[s + i]);
        uint2 u = __ldg(H + (size_t)p.x * 16 + q);
        acc4(acc, __int_as_float(p.y), h4_to_f4(u));
    }
    acc.x = fmaxf(acc.x, 0.f); acc.y = fmaxf(acc.y, 0.f);
    acc.z = fmaxf(acc.z, 0.f); acc.w = fmaxf(acc.w, 0.f);
    ((uint2*)g_h2h)[(size_t)row * 16 + q] = f4_to_h4(acc);
}

// ---------------- dense: z1 = h2 @ W2 + b2 (fp16 in, fp16 out, fp32 math) ----------------
#define PADK 68
__global__ __launch_bounds__(256) void k_dense(const float* __restrict__ W2,
                                               const float* __restrict__ b2) {
    __shared__ float sW2t[NLAB * PADK];   // [j][k]
    __shared__ float sb2[NLAB];
    int tid = threadIdx.x;
    for (int i = tid; i < HID * NLAB; i += 256) {
        int k = i / NLAB, j = i - k * NLAB;
        sW2t[j * PADK + k] = W2[i];
    }
    if (tid < NLAB) sb2[tid] = b2[tid];
    __syncthreads();

    int j0 = (tid & 3) * 10;
    int n0 = (blockIdx.x * 64 + (tid >> 2)) * 4;

    float acc[4][10];
#pragma unroll
    for (int nn = 0; nn < 4; nn++)
#pragma unroll
        for (int j = 0; j < 10; j++) acc[nn][j] = sb2[j0 + j];

    const uint2* H = (const uint2*)g_h2h;     // 16 uint2 per h2 row
#pragma unroll
    for (int k4 = 0; k4 < HID; k4 += 4) {
        float4 h[4];
#pragma unroll
        for (int nn = 0; nn < 4; nn++) {
            int nd = n0 + nn;
            h[nn] = (nd < N_NODES)
                  ? h4_to_f4(__ldg(H + (size_t)nd * 16 + (k4 >> 2)))
                  : make_float4(0.f, 0.f, 0.f, 0.f);
        }
#pragma unroll
        for (int j = 0; j < 10; j++) {
            float4 wv = *(const float4*)&sW2t[(j0 + j) * PADK + k4];
#pragma unroll
            for (int nn = 0; nn < 4; nn++)
                acc[nn][j] += h[nn].x * wv.x + h[nn].y * wv.y + h[nn].z * wv.z + h[nn].w * wv.w;
        }
    }
    unsigned short* Z = (unsigned short*)g_z1h;
#pragma unroll
    for (int nn = 0; nn < 4; nn++) {
        int nd = n0 + nn;
        if (nd >= N_NODES) break;
        unsigned* zp = (unsigned*)(Z + (size_t)nd * NLAB + j0);   // j0*2 bytes: 4B-aligned
#pragma unroll
        for (int j = 0; j < 10; j += 2) {
            __half2 hp = __floats2half2_rn(acc[nn][j], acc[nn][j + 1]);
            zp[j >> 1] = *(unsigned*)&hp;
        }
    }
}

// ---------------- final propagate + fused log-softmax ----------------
// out[row] = log_softmax( sum_i w_i * z1[col_i] ); lanes 0..9 gather 4 halves each.
__global__ __launch_bounds__(256) void k_edge40_lsm(float* __restrict__ out, int nnz) {
    int tid = threadIdx.x;
    int row = blockIdx.x * 16 + (tid >> 4);
    int q = tid & 15;
    if (row >= N_NODES) return;
    int s = g_start[N_NODES + row] - nnz;
    int n = g_cnt[N_NODES + row];
    bool act = (q < 10);
    const uint2* Z = (const uint2*)g_z1h;     // 10 uint2 per z row
    float4 acc = make_float4(0.f, 0.f, 0.f, 0.f);
    int i = 0;
    for (; i + 4 <= n; i += 4) {
        int2 p0 = __ldg(&g_ebuf[s + i]);
        int2 p1 = __ldg(&g_ebuf[s + i + 1]);
        int2 p2 = __ldg(&g_ebuf[s + i + 2]);
        int2 p3 = __ldg(&g_ebuf[s + i + 3]);
        if (act) {
            uint2 u0 = __ldg(Z + (size_t)p0.x * 10 + q);
            uint2 u1 = __ldg(Z + (size_t)p1.x * 10 + q);
            uint2 u2 = __ldg(Z + (size_t)p2.x * 10 + q);
            uint2 u3 = __ldg(Z + (size_t)p3.x * 10 + q);
            acc4(acc, __int_as_float(p0.y), h4_to_f4(u0));
            acc4(acc, __int_as_float(p1.y), h4_to_f4(u1));
            acc4(acc, __int_as_float(p2.y), h4_to_f4(u2));
            acc4(acc, __int_as_float(p3.y), h4_to_f4(u3));
        }
    }
    for (; i < n; i++) {
        int2 p = __ldg(&g_ebuf[s + i]);
        if (act) {
            uint2 u = __ldg(Z + (size_t)p.x * 10 + q);
            acc4(acc, __int_as_float(p.y), h4_to_f4(u));
        }
    }
    float m = act ? fmaxf(fmaxf(acc.x, acc.y), fmaxf(acc.z, acc.w)) : -1e30f;
#pragma unroll
    for (int o = 1; o < 16; o <<= 1) m = fmaxf(m, __shfl_xor_sync(0xFFFFFFFFu, m, o, 16));
    float es = act ? (expf(acc.x - m) + expf(acc.y - m) + expf(acc.z - m) + expf(acc.w - m)) : 0.f;
#pragma unroll
    for (int o = 1; o < 16; o <<= 1) es += __shfl_xor_sync(0xFFFFFFFFu, es, o, 16);
    float l = m + logf(es);
    if (act) {
        *((float4*)(out + (size_t)row * NLAB) + q) =
            make_float4(acc.x - l, acc.y - l, acc.z - l, acc.w - l);
    }
}

extern "C" void kernel_launch(void* const* d_in, const int* in_sizes, int n_in,
                              void* d_out, int out_size) {
    // Bind inputs by element count (pairwise distinct); indices are int32.
    const int* fi = 0; const float* fv = 0;
    const int* ei = 0; const float* ew = 0;
    const float *W1 = 0, *b1 = 0, *W2 = 0, *b2 = 0;
    int nnz = 0, ne = 0;
    for (int i = 0; i < n_in; i++) {
        int s = in_sizes[i];
        const void* p = d_in[i];
        if (s == 2 * MAX_NNZ)            { fi = (const int*)p; }
        else if (s == MAX_NNZ)           { fv = (const float*)p; nnz = s; }
        else if (s == 2 * MAX_NE)        { ei = (const int*)p; }
        else if (s == MAX_NE)            { ew = (const float*)p; ne = s; }
        else if (s == N_FEATS * HID)     { W1 = (const float*)p; }
        else if (s == HID)               { b1 = (const float*)p; }
        else if (s == HID * NLAB)        { W2 = (const float*)p; }
        else if (s == NLAB)              { b2 = (const float*)p; }
    }
    float* out = (float*)d_out;
    int tot = nnz + ne;

    // CSR build (counting sort by row) + W1 fp16 convert
    k_zero<<<(N_SEG + 255) / 256, 256>>>(W1);
    k_hist<<<(tot + 255) / 256, 256>>>(fi, nnz, ei, ne);
    k_scan1<<<NBLK, 1024>>>();
    k_scan23<<<(N_SEG + 255) / 256, 256>>>();
    k_scat<<<(tot + 255) / 256, 256>>>(fi, fv, nnz, ei, ew, ne);

    // GCN forward (gather-only, no atomics)
    k_feat_csr<<<(N_NODES + 15) / 16, 256>>>(b1);
    k_edge64_csr<<<(N_NODES + 15) / 16, 256>>>(nnz);
    k_dense<<<(N_NODES + 255) / 256, 256>>>(W2, b2);
    k_edge40_lsm<<<(N_NODES + 15) / 16, 256>>>(out, nnz);
}

// round 12
// speedup vs baseline: 2.6122x; 1.0107x over previous
#include <cuda_runtime.h>
#include <cuda_fp16.h>
#include <math.h>

#define N_NODES 100000
#define N_FEATS 2048
#define HID 64
#define NLAB 40
#define N_SEG (2 * N_NODES)
#define MAX_NNZ 2500000
#define MAX_NE  1700000

// ---- scratch (static: no allocations; zero-init at load) ----
__device__ __align__(16) __half2 g_W1h[N_FEATS * HID / 2];   // fp16 W1 (256 KB)
__device__ __align__(16) __half2 g_h1h[N_NODES * HID / 2];   // h1 fp16 (12.8 MB)
__device__ __align__(16) __half2 g_h2h[N_NODES * HID / 2];   // h2 fp16, relu'ed
__device__ __align__(16) __half2 g_z1h[N_NODES * NLAB / 2];  // z1 fp16 (8 MB)
__device__ int g_cnt[N_SEG];        // invariant: all-zero at kernel_launch entry
__device__ int g_start[N_SEG];
__device__ int g_cursor[N_SEG];
__device__ int gTotF, gTotE;        // scan bases; reset by k_dense each call
__device__ unsigned g_fbuf[MAX_NNZ];                  // (col<<16)|fp16(val), by row
__device__ __align__(8) int2 g_ebuf[MAX_NE];          // (col, w bits), by row

__device__ __forceinline__ int clamp_i(int i, int n) {
    i = i < 0 ? 0 : i;
    return i >= n ? n - 1 : i;
}

__device__ __forceinline__ float4 h4lo(uint4 u) {
    float2 a = __half22float2(*(__half2*)&u.x);
    float2 b = __half22float2(*(__half2*)&u.y);
    return make_float4(a.x, a.y, b.x, b.y);
}
__device__ __forceinline__ float4 h4hi(uint4 u) {
    float2 a = __half22float2(*(__half2*)&u.z);
    float2 b = __half22float2(*(__half2*)&u.w);
    return make_float4(a.x, a.y, b.x, b.y);
}
__device__ __forceinline__ void acc8(float4& a, float4& b, float s, uint4 u) {
    float4 lo = h4lo(u), hi = h4hi(u);
    a.x += s * lo.x; a.y += s * lo.y; a.z += s * lo.z; a.w += s * lo.w;
    b.x += s * hi.x; b.y += s * hi.y; b.z += s * hi.z; b.w += s * hi.w;
}
__device__ __forceinline__ uint4 f8_to_h8(float4 a, float4 b) {
    __half2 p = __floats2half2_rn(a.x, a.y), q = __floats2half2_rn(a.z, a.w);
    __half2 r = __floats2half2_rn(b.x, b.y), s = __floats2half2_rn(b.z, b.w);
    uint4 u;
    u.x = *(unsigned*)&p; u.y = *(unsigned*)&q;
    u.z = *(unsigned*)&r; u.w = *(unsigned*)&s;
    return u;
}

// ---------------- build: histogram (+ W1 fp16 convert folded in) ----------------
__global__ void k_hist(const int* __restrict__ fi, int nnz,
                       const int* __restrict__ ei, int ne,
                       const float* __restrict__ W1) {
    int e = blockIdx.x * blockDim.x + threadIdx.x;
    if (e < N_FEATS * HID / 2) {
        float2 f = __ldg((const float2*)W1 + e);
        g_W1h[e] = __floats2half2_rn(f.x, f.y);
    }
    if (e < nnz) {
        atomicAdd(&g_cnt[clamp_i(__ldg(&fi[e]), N_NODES)], 1);
    } else if (e < nnz + ne) {
        int t = e - nnz;
        atomicAdd(&g_cnt[N_NODES + clamp_i(__ldg(&ei[t]), N_NODES)], 1);
    }
}

// ---------------- single-kernel scan: 250 blocks x 800 (125 feat | 125 edge) ----------------
__global__ __launch_bounds__(800) void k_scan() {
    int tid = threadIdx.x;
    int bid = blockIdx.x;
    int i = bid * 800 + tid;                 // 250*800 = 200000 = N_SEG exactly
    int v = g_cnt[i];
    int lane = tid & 31, wid = tid >> 5;
    int x = v;
#pragma unroll
    for (int o = 1; o < 32; o <<= 1) {
        int y = __shfl_up_sync(0xFFFFFFFFu, x, o);
        if (lane >= o) x += y;
    }
    __shared__ int ws[25];
    __shared__ int sbase;
    if (lane == 31) ws[wid] = x;
    __syncthreads();
    if (tid < 32) {
        int s = (tid < 25) ? ws[tid] : 0;
#pragma unroll
        for (int o = 1; o < 32; o <<= 1) {
            int y = __shfl_up_sync(0xFFFFFFFFu, s, o);
            if (tid >= o) s += y;
        }
        if (tid < 25) ws[tid] = s;           // inclusive scan of warp sums
        if (tid == 24) sbase = atomicAdd((bid >= 125) ? &gTotE : &gTotF, s);
    }
    __syncthreads();
    int incl = x + (wid ? ws[wid - 1] : 0);
    int st = sbase + incl - v;               // exclusive start (fbuf- or ebuf-relative)
    g_start[i] = st;
    g_cursor[i] = st;
}

// ---------------- scatter: features (packed 4B) then edges (8B) ----------------
__global__ void k_scat(const int* __restrict__ fi, const float* __restrict__ fv, int nnz,
                       const int* __restrict__ ei, const float* __restrict__ ew, int ne) {
    int e = blockIdx.x * blockDim.x + threadIdx.x;
    if (e < nnz) {
        int row = clamp_i(__ldg(&fi[e]), N_NODES);
        int col = clamp_i(__ldg(&fi[nnz + e]), N_FEATS);
        __half hv = __float2half_rn(__ldg(&fv[e]));
        int pos = atomicAdd(&g_cursor[row], 1);
        g_fbuf[pos] = ((unsigned)col << 16) | (unsigned)*(unsigned short*)&hv;
    } else if (e < nnz + ne) {
        int t = e - nnz;
        int row = clamp_i(__ldg(&ei[t]), N_NODES);
        int col = clamp_i(__ldg(&ei[ne + t]), N_NODES);
        float wv = __ldg(&ew[t]);
        int pos = atomicAdd(&g_cursor[N_NODES + row], 1);    // ebuf-relative
        g_ebuf[pos] = make_int2(col, __float_as_int(wv));
    }
}

// ---------------- gather-only SpMMs: 8 lanes x uint4(16B) per row ----------------
__device__ __forceinline__ float fent_val(unsigned p) {
    unsigned short b = (unsigned short)(p & 0xFFFFu);
    return __half2float(*(__half*)&b);
}

// h1[row] = b1 + sum_i val_i * W1[col_i, :]
__global__ __launch_bounds__(256) void k_feat_csr(const float* __restrict__ b1) {
    int tid = threadIdx.x;
    int row = blockIdx.x * 32 + (tid >> 3);
    int q = tid & 7;
    if (row >= N_NODES) return;
    int s = g_start[row];
    int n = g_cnt[row];
    float4 accA = __ldg((const float4*)b1 + q * 2);
    float4 accB = __ldg((const float4*)b1 + q * 2 + 1);
    const uint4* W = (const uint4*)g_W1h;     // 8 uint4 per W1 row
    int i = 0;
    for (; i + 4 <= n; i += 4) {
        unsigned p0 = __ldg(&g_fbuf[s + i]);
        unsigned p1 = __ldg(&g_fbuf[s + i + 1]);
        unsigned p2 = __ldg(&g_fbuf[s + i + 2]);
        unsigned p3 = __ldg(&g_fbuf[s + i + 3]);
        uint4 u0 = __ldg(W + (size_t)(p0 >> 16) * 8 + q);
        uint4 u1 = __ldg(W + (size_t)(p1 >> 16) * 8 + q);
        uint4 u2 = __ldg(W + (size_t)(p2 >> 16) * 8 + q);
        uint4 u3 = __ldg(W + (size_t)(p3 >> 16) * 8 + q);
        acc8(accA, accB, fent_val(p0), u0);
        acc8(accA, accB, fent_val(p1), u1);
        acc8(accA, accB, fent_val(p2), u2);
        acc8(accA, accB, fent_val(p3), u3);
    }
    for (; i < n; i++) {
        unsigned p = __ldg(&g_fbuf[s + i]);
        uint4 u = __ldg(W + (size_t)(p >> 16) * 8 + q);
        acc8(accA, accB, fent_val(p), u);
    }
    ((uint4*)g_h1h)[(size_t)row * 8 + q] = f8_to_h8(accA, accB);
    if (q == 0) g_cnt[row] = 0;               // restore invariant for next call
}

// h2[row] = relu( sum_i w_i * h1[col_i] )
__global__ __launch_bounds__(256) void k_edge64_csr() {
    int tid = threadIdx.x;
    int row = blockIdx.x * 32 + (tid >> 3);
    int q = tid & 7;
    if (row >= N_NODES) return;
    int s = g_start[N_NODES + row];
    int n = g_cnt[N_NODES + row];
    const uint4* H = (const uint4*)g_h1h;
    float4 accA = make_float4(0.f, 0.f, 0.f, 0.f);
    float4 accB = make_float4(0.f, 0.f, 0.f, 0.f);
    int i = 0;
    for (; i + 4 <= n; i += 4) {
        int2 p0 = __ldg(&g_ebuf[s + i]);
        int2 p1 = __ldg(&g_ebuf[s + i + 1]);
        int2 p2 = __ldg(&g_ebuf[s + i + 2]);
        int2 p3 = __ldg(&g_ebuf[s + i + 3]);
        uint4 u0 = __ldg(H + (size_t)p0.x * 8 + q);
        uint4 u1 = __ldg(H + (size_t)p1.x * 8 + q);
        uint4 u2 = __ldg(H + (size_t)p2.x * 8 + q);
        uint4 u3 = __ldg(H + (size_t)p3.x * 8 + q);
        acc8(accA, accB, __int_as_float(p0.y), u0);
        acc8(accA, accB, __int_as_float(p1.y), u1);
        acc8(accA, accB, __int_as_float(p2.y), u2);
        acc8(accA, accB, __int_as_float(p3.y), u3);
    }
    for (; i < n; i++) {
        int2 p = __ldg(&g_ebuf[s + i]);
        uint4 u = __ldg(H + (size_t)p.x * 8 + q);
        acc8(accA, accB, __int_as_float(p.y), u);
    }
    accA.x = fmaxf(accA.x, 0.f); accA.y = fmaxf(accA.y, 0.f);
    accA.z = fmaxf(accA.z, 0.f); accA.w = fmaxf(accA.w, 0.f);
    accB.x = fmaxf(accB.x, 0.f); accB.y = fmaxf(accB.y, 0.f);
    accB.z = fmaxf(accB.z, 0.f); accB.w = fmaxf(accB.w, 0.f);
    ((uint4*)g_h2h)[(size_t)row * 8 + q] = f8_to_h8(accA, accB);
}

// ---------------- dense: z1 = h2 @ W2 + b2 (fp16 in/out, fp32 math) ----------------
#define PADK 68
__global__ __launch_bounds__(256) void k_dense(const float* __restrict__ W2,
                                               const float* __restrict__ b2) {
    if (blockIdx.x == 0 && threadIdx.x == 0) { gTotF = 0; gTotE = 0; }  // reset scan bases
    __shared__ float sW2t[NLAB * PADK];   // [j][k]
    __shared__ float sb2[NLAB];
    int tid = threadIdx.x;
    for (int i = tid; i < HID * NLAB; i += 256) {
        int k = i / NLAB, j = i - k * NLAB;
        sW2t[j * PADK + k] = W2[i];
    }
    if (tid < NLAB) sb2[tid] = b2[tid];
    __syncthreads();

    int j0 = (tid & 3) * 10;
    int n0 = (blockIdx.x * 64 + (tid >> 2)) * 4;

    float acc[4][10];
#pragma unroll
    for (int nn = 0; nn < 4; nn++)
#pragma unroll
        for (int j = 0; j < 10; j++) acc[nn][j] = sb2[j0 + j];

    const uint2* H = (const uint2*)g_h2h;     // 16 uint2 per h2 row
#pragma unroll
    for (int k4 = 0; k4 < HID; k4 += 4) {
        float4 h[4];
#pragma unroll
        for (int nn = 0; nn < 4; nn++) {
            int nd = n0 + nn;
            if (nd < N_NODES) {
                uint2 u = __ldg(H + (size_t)nd * 16 + (k4 >> 2));
                float2 a = __half22float2(*(__half2*)&u.x);
                float2 b = __half22float2(*(__half2*)&u.y);
                h[nn] = make_float4(a.x, a.y, b.x, b.y);
            } else h[nn] = make_float4(0.f, 0.f, 0.f, 0.f);
        }
#pragma unroll
        for (int j = 0; j < 10; j++) {
            float4 wv = *(const float4*)&sW2t[(j0 + j) * PADK + k4];
#pragma unroll
            for (int nn = 0; nn < 4; nn++)
                acc[nn][j] += h[nn].x * wv.x + h[nn].y * wv.y + h[nn].z * wv.z + h[nn].w * wv.w;
        }
    }
    unsigned short* Z = (unsigned short*)g_z1h;
#pragma unroll
    for (int nn = 0; nn < 4; nn++) {
        int nd = n0 + nn;
        if (nd >= N_NODES) break;
        unsigned* zp = (unsigned*)(Z + (size_t)nd * NLAB + j0);
#pragma unroll
        for (int j = 0; j < 10; j += 2) {
            __half2 hp = __floats2half2_rn(acc[nn][j], acc[nn][j + 1]);
            zp[j >> 1] = *(unsigned*)&hp;
        }
    }
}

// ---------------- final propagate + fused log-softmax (8-lane groups, 5 active) --------
__global__ __launch_bounds__(256) void k_edge40_lsm(float* __restrict__ out) {
    int tid = threadIdx.x;
    int row = blockIdx.x * 32 + (tid >> 3);
    int q = tid & 7;
    if (row >= N_NODES) return;
    int s = g_start[N_NODES + row];
    int n = g_cnt[N_NODES + row];
    bool act = (q < 5);
    const uint4* Z = (const uint4*)g_z1h;     // 5 uint4 per z row
    float4 accA = make_float4(0.f, 0.f, 0.f, 0.f);
    float4 accB = make_float4(0.f, 0.f, 0.f, 0.f);
    int i = 0;
    for (; i + 4 <= n; i += 4) {
        int2 p0 = __ldg(&g_ebuf[s + i]);
        int2 p1 = __ldg(&g_ebuf[s + i + 1]);
        int2 p2 = __ldg(&g_ebuf[s + i + 2]);
        int2 p3 = __ldg(&g_ebuf[s + i + 3]);
        if (act) {
            uint4 u0 = __ldg(Z + (size_t)p0.x * 5 + q);
            uint4 u1 = __ldg(Z + (size_t)p1.x * 5 + q);
            uint4 u2 = __ldg(Z + (size_t)p2.x * 5 + q);
            uint4 u3 = __ldg(Z + (size_t)p3.x * 5 + q);
            acc8(accA, accB, __int_as_float(p0.y), u0);
            acc8(accA, accB, __int_as_float(p1.y), u1);
            acc8(accA, accB, __int_as_float(p2.y), u2);
            acc8(accA, accB, __int_as_float(p3.y), u3);
        }
    }
    for (; i < n; i++) {
        int2 p = __ldg(&g_ebuf[s + i]);
        if (act) {
            uint4 u = __ldg(Z + (size_t)p.x * 5 + q);
            acc8(accA, accB, __int_as_float(p.y), u);
        }
    }
    // log-softmax across the 8-lane group (lanes 0..4 hold the 40 values)
    float m = act ? fmaxf(fmaxf(fmaxf(accA.x, accA.y), fmaxf(accA.z, accA.w)),
                          fmaxf(fmaxf(accB.x, accB.y), fmaxf(accB.z, accB.w))) : -1e30f;
#pragma unroll
    for (int o = 1; o < 8; o <<= 1) m = fmaxf(m, __shfl_xor_sync(0xFFFFFFFFu, m, o, 8));
    float es = act ? (expf(accA.x - m) + expf(accA.y - m) + expf(accA.z - m) + expf(accA.w - m) +
                      expf(accB.x - m) + expf(accB.y - m) + expf(accB.z - m) + expf(accB.w - m)) : 0.f;
#pragma unroll
    for (int o = 1; o < 8; o <<= 1) es += __shfl_xor_sync(0xFFFFFFFFu, es, o, 8);
    float l = m + logf(es);
    if (act) {
        float* op = out + (size_t)row * NLAB + q * 8;
        *(float4*)op = make_float4(accA.x - l, accA.y - l, accA.z - l, accA.w - l);
        *(float4*)(op + 4) = make_float4(accB.x - l, accB.y - l, accB.z - l, accB.w - l);
    }
    if (q == 0) g_cnt[N_NODES + row] = 0;     // restore invariant for next call
}

extern "C" void kernel_launch(void* const* d_in, const int* in_sizes, int n_in,
                              void* d_out, int out_size) {
    // Bind inputs by element count (pairwise distinct); indices are int32.
    const int* fi = 0; const float* fv = 0;
    const int* ei = 0; const float* ew = 0;
    const float *W1 = 0, *b1 = 0, *W2 = 0, *b2 = 0;
    int nnz = 0, ne = 0;
    for (int i = 0; i < n_in; i++) {
        int s = in_sizes[i];
        const void* p = d_in[i];
        if (s == 2 * MAX_NNZ)            { fi = (const int*)p; }
        else if (s == MAX_NNZ)           { fv = (const float*)p; nnz = s; }
        else if (s == 2 * MAX_NE)        { ei = (const int*)p; }
        else if (s == MAX_NE)            { ew = (const float*)p; ne = s; }
        else if (s == N_FEATS * HID)     { W1 = (const float*)p; }
        else if (s == HID)               { b1 = (const float*)p; }
        else if (s == HID * NLAB)        { W2 = (const float*)p; }
        else if (s == NLAB)              { b2 = (const float*)p; }
    }
    float* out = (float*)d_out;
    int tot = nnz + ne;

    // CSR build (g_cnt arrives all-zero: first call by static init, later calls
    // restored by k_feat_csr / k_edge40_lsm of the previous call)
    k_hist<<<(tot + 255) / 256, 256>>>(fi, nnz, ei, ne, W1);
    k_scan<<<250, 800>>>();
    k_scat<<<(tot + 255) / 256, 256>>>(fi, fv, nnz, ei, ew, ne);

    // GCN forward (gather-only, no atomics)
    k_feat_csr<<<(N_NODES + 31) / 32, 256>>>(b1);
    k_edge64_csr<<<(N_NODES + 31) / 32, 256>>>();
    k_dense<<<(N_NODES + 255) / 256, 256>>>(W2, b2);
    k_edge40_lsm<<<(N_NODES + 31) / 32, 256>>>(out);
}

// round 13
// speedup vs baseline: 2.8116x; 1.0763x over previous
#include <cuda_runtime.h>
#include <cuda_fp16.h>
#include <math.h>

#define N_NODES 100000
#define N_FEATS 2048
#define HID 64
#define NLAB 40
#define N_SEG (2 * N_NODES)
#define MAX_NNZ 2500000
#define MAX_NE  1700000

// ---- scratch (static: no allocations; zero-init at load) ----
__device__ __align__(16) __half2 g_W1h[N_FEATS * HID / 2];   // fp16 W1 (256 KB)
__device__ __align__(16) __half2 g_h1h[N_NODES * HID / 2];   // h1 fp16 (12.8 MB)
__device__ __align__(16) __half2 g_h2h[N_NODES * HID / 2];   // h2 fp16, relu'ed
__device__ __align__(16) __half2 g_z1h[N_NODES * NLAB / 2];  // z1 fp16 (8 MB)
__device__ int g_cnt[N_SEG];        // invariant: all-zero at kernel_launch entry
__device__ int g_start[N_SEG];
__device__ int g_cursor[N_SEG];
__device__ int gTotF, gTotE;        // scan bases; reset by k_dense each call
__device__ unsigned g_fbuf[MAX_NNZ];                  // (col<<16)|fp16(val), by row
__device__ __align__(8) int2 g_ebuf[MAX_NE];          // (col, w bits), by row

__device__ __forceinline__ int clamp_i(int i, int n) {
    i = i < 0 ? 0 : i;
    return i >= n ? n - 1 : i;
}

__device__ __forceinline__ float4 h4lo(uint4 u) {
    float2 a = __half22float2(*(__half2*)&u.x);
    float2 b = __half22float2(*(__half2*)&u.y);
    return make_float4(a.x, a.y, b.x, b.y);
}
__device__ __forceinline__ float4 h4hi(uint4 u) {
    float2 a = __half22float2(*(__half2*)&u.z);
    float2 b = __half22float2(*(__half2*)&u.w);
    return make_float4(a.x, a.y, b.x, b.y);
}
__device__ __forceinline__ void acc8(float4& a, float4& b, float s, uint4 u) {
    float4 lo = h4lo(u), hi = h4hi(u);
    a.x += s * lo.x; a.y += s * lo.y; a.z += s * lo.z; a.w += s * lo.w;
    b.x += s * hi.x; b.y += s * hi.y; b.z += s * hi.z; b.w += s * hi.w;
}
__device__ __forceinline__ uint4 f8_to_h8(float4 a, float4 b) {
    __half2 p = __floats2half2_rn(a.x, a.y), q = __floats2half2_rn(a.z, a.w);
    __half2 r = __floats2half2_rn(b.x, b.y), s = __floats2half2_rn(b.z, b.w);
    uint4 u;
    u.x = *(unsigned*)&p; u.y = *(unsigned*)&q;
    u.z = *(unsigned*)&r; u.w = *(unsigned*)&s;
    return u;
}

// fp16 HFMA2 accumulate: acc += v2 * u  (4 HFMA2, no unpack)
__device__ __forceinline__ void hacc8(uint4& a, __half2 v2, uint4 u) {
    *(__half2*)&a.x = __hfma2(v2, *(__half2*)&u.x, *(__half2*)&a.x);
    *(__half2*)&a.y = __hfma2(v2, *(__half2*)&u.y, *(__half2*)&a.y);
    *(__half2*)&a.z = __hfma2(v2, *(__half2*)&u.z, *(__half2*)&a.z);
    *(__half2*)&a.w = __hfma2(v2, *(__half2*)&u.w, *(__half2*)&a.w);
}

// ---------------- build: histogram (+ W1 fp16 convert folded in) ----------------
__global__ void k_hist(const int* __restrict__ fi, int nnz,
                       const int* __restrict__ ei, int ne,
                       const float* __restrict__ W1) {
    int e = blockIdx.x * blockDim.x + threadIdx.x;
    if (e < N_FEATS * HID / 2) {
        float2 f = __ldg((const float2*)W1 + e);
        g_W1h[e] = __floats2half2_rn(f.x, f.y);
    }
    if (e < nnz) {
        atomicAdd(&g_cnt[clamp_i(__ldg(&fi[e]), N_NODES)], 1);
    } else if (e < nnz + ne) {
        int t = e - nnz;
        atomicAdd(&g_cnt[N_NODES + clamp_i(__ldg(&ei[t]), N_NODES)], 1);
    }
}

// ---------------- single-kernel scan: 250 blocks x 800 (125 feat | 125 edge) ----------------
__global__ __launch_bounds__(800) void k_scan() {
    int tid = threadIdx.x;
    int bid = blockIdx.x;
    int i = bid * 800 + tid;                 // 250*800 = 200000 = N_SEG exactly
    int v = g_cnt[i];
    int lane = tid & 31, wid = tid >> 5;
    int x = v;
#pragma unroll
    for (int o = 1; o < 32; o <<= 1) {
        int y = __shfl_up_sync(0xFFFFFFFFu, x, o);
        if (lane >= o) x += y;
    }
    __shared__ int ws[25];
    __shared__ int sbase;
    if (lane == 31) ws[wid] = x;
    __syncthreads();
    if (tid < 32) {
        int s = (tid < 25) ? ws[tid] : 0;
#pragma unroll
        for (int o = 1; o < 32; o <<= 1) {
            int y = __shfl_up_sync(0xFFFFFFFFu, s, o);
            if (tid >= o) s += y;
        }
        if (tid < 25) ws[tid] = s;           // inclusive scan of warp sums
        if (tid == 24) sbase = atomicAdd((bid >= 125) ? &gTotE : &gTotF, s);
    }
    __syncthreads();
    int incl = x + (wid ? ws[wid - 1] : 0);
    int st = sbase + incl - v;               // exclusive start (fbuf- or ebuf-relative)
    g_start[i] = st;
    g_cursor[i] = st;
}

// ---------------- scatter: features (packed 4B) then edges (8B) ----------------
__global__ void k_scat(const int* __restrict__ fi, const float* __restrict__ fv, int nnz,
                       const int* __restrict__ ei, const float* __restrict__ ew, int ne) {
    int e = blockIdx.x * blockDim.x + threadIdx.x;
    if (e < nnz) {
        int row = clamp_i(__ldg(&fi[e]), N_NODES);
        int col = clamp_i(__ldg(&fi[nnz + e]), N_FEATS);
        __half hv = __float2half_rn(__ldg(&fv[e]));
        int pos = atomicAdd(&g_cursor[row], 1);
        g_fbuf[pos] = ((unsigned)col << 16) | (unsigned)*(unsigned short*)&hv;
    } else if (e < nnz + ne) {
        int t = e - nnz;
        int row = clamp_i(__ldg(&ei[t]), N_NODES);
        int col = clamp_i(__ldg(&ei[ne + t]), N_NODES);
        float wv = __ldg(&ew[t]);
        int pos = atomicAdd(&g_cursor[N_NODES + row], 1);    // ebuf-relative
        g_ebuf[pos] = make_int2(col, __float_as_int(wv));
    }
}

// ---------------- gather-only SpMMs: 8 lanes x uint4(16B) per row ----------------
// h1[row] = b1 + sum_i val_i * W1[col_i, :]   (fp16 HFMA2 accumulation)
__global__ __launch_bounds__(256) void k_feat_csr(const float* __restrict__ b1) {
    int tid = threadIdx.x;
    int row = blockIdx.x * 32 + (tid >> 3);
    int q = tid & 7;
    if (row >= N_NODES) return;
    int s = g_start[row];
    int n = g_cnt[row];
    uint4 acc = f8_to_h8(__ldg((const float4*)b1 + q * 2),
                         __ldg((const float4*)b1 + q * 2 + 1));
    const uint4* W = (const uint4*)g_W1h;     // 8 uint4 per W1 row
    int i = 0;
    for (; i + 4 <= n; i += 4) {
        unsigned p0 = __ldg(&g_fbuf[s + i]);
        unsigned p1 = __ldg(&g_fbuf[s + i + 1]);
        unsigned p2 = __ldg(&g_fbuf[s + i + 2]);
        unsigned p3 = __ldg(&g_fbuf[s + i + 3]);
        uint4 u0 = __ldg(W + (size_t)(p0 >> 16) * 8 + q);
        uint4 u1 = __ldg(W + (size_t)(p1 >> 16) * 8 + q);
        uint4 u2 = __ldg(W + (size_t)(p2 >> 16) * 8 + q);
        uint4 u3 = __ldg(W + (size_t)(p3 >> 16) * 8 + q);
        unsigned short b0 = (unsigned short)p0, b1s = (unsigned short)p1;
        unsigned short b2 = (unsigned short)p2, b3 = (unsigned short)p3;
        hacc8(acc, __half2half2(*(__half*)&b0), u0);
        hacc8(acc, __half2half2(*(__half*)&b1s), u1);
        hacc8(acc, __half2half2(*(__half*)&b2), u2);
        hacc8(acc, __half2half2(*(__half*)&b3), u3);
    }
    for (; i < n; i++) {
        unsigned p = __ldg(&g_fbuf[s + i]);
        uint4 u = __ldg(W + (size_t)(p >> 16) * 8 + q);
        unsigned short b = (unsigned short)p;
        hacc8(acc, __half2half2(*(__half*)&b), u);
    }
    ((uint4*)g_h1h)[(size_t)row * 8 + q] = acc;
    if (q == 0) g_cnt[row] = 0;               // restore invariant for next call
}

// h2[row] = relu( sum_i w_i * h1[col_i] )   (fp16 HFMA2 accumulation)
__global__ __launch_bounds__(256) void k_edge64_csr() {
    int tid = threadIdx.x;
    int row = blockIdx.x * 32 + (tid >> 3);
    int q = tid & 7;
    if (row >= N_NODES) return;
    int s = g_start[N_NODES + row];
    int n = g_cnt[N_NODES + row];
    const uint4* H = (const uint4*)g_h1h;
    uint4 acc = make_uint4(0u, 0u, 0u, 0u);   // fp16 zeros
    int i = 0;
    for (; i + 4 <= n; i += 4) {
        int2 p0 = __ldg(&g_ebuf[s + i]);
        int2 p1 = __ldg(&g_ebuf[s + i + 1]);
        int2 p2 = __ldg(&g_ebuf[s + i + 2]);
        int2 p3 = __ldg(&g_ebuf[s + i + 3]);
        uint4 u0 = __ldg(H + (size_t)p0.x * 8 + q);
        uint4 u1 = __ldg(H + (size_t)p1.x * 8 + q);
        uint4 u2 = __ldg(H + (size_t)p2.x * 8 + q);
        uint4 u3 = __ldg(H + (size_t)p3.x * 8 + q);
        hacc8(acc, __float2half2_rn(__int_as_float(p0.y)), u0);
        hacc8(acc, __float2half2_rn(__int_as_float(p1.y)), u1);
        hacc8(acc, __float2half2_rn(__int_as_float(p2.y)), u2);
        hacc8(acc, __float2half2_rn(__int_as_float(p3.y)), u3);
    }
    for (; i < n; i++) {
        int2 p = __ldg(&g_ebuf[s + i]);
        uint4 u = __ldg(H + (size_t)p.x * 8 + q);
        hacc8(acc, __float2half2_rn(__int_as_float(p.y)), u);
    }
    // relu in fp16
    __half2 z2 = __float2half2_rn(0.f);
    *(__half2*)&acc.x = __hmax2(*(__half2*)&acc.x, z2);
    *(__half2*)&acc.y = __hmax2(*(__half2*)&acc.y, z2);
    *(__half2*)&acc.z = __hmax2(*(__half2*)&acc.z, z2);
    *(__half2*)&acc.w = __hmax2(*(__half2*)&acc.w, z2);
    ((uint4*)g_h2h)[(size_t)row * 8 + q] = acc;
}

// ---------------- dense: z1 = h2 @ W2 + b2 (fp16 in/out, fp32 math) ----------------
#define PADK 68
__global__ __launch_bounds__(256) void k_dense(const float* __restrict__ W2,
                                               const float* __restrict__ b2) {
    if (blockIdx.x == 0 && threadIdx.x == 0) { gTotF = 0; gTotE = 0; }  // reset scan bases
    __shared__ float sW2t[NLAB * PADK];   // [j][k]
    __shared__ float sb2[NLAB];
    int tid = threadIdx.x;
    for (int i = tid; i < HID * NLAB; i += 256) {
        int k = i / NLAB, j = i - k * NLAB;
        sW2t[j * PADK + k] = W2[i];
    }
    if (tid < NLAB) sb2[tid] = b2[tid];
    __syncthreads();

    int j0 = (tid & 3) * 10;
    int n0 = (blockIdx.x * 64 + (tid >> 2)) * 4;

    float acc[4][10];
#pragma unroll
    for (int nn = 0; nn < 4; nn++)
#pragma unroll
        for (int j = 0; j < 10; j++) acc[nn][j] = sb2[j0 + j];

    const uint2* H = (const uint2*)g_h2h;     // 16 uint2 per h2 row
#pragma unroll
    for (int k4 = 0; k4 < HID; k4 += 4) {
        float4 h[4];
#pragma unroll
        for (int nn = 0; nn < 4; nn++) {
            int nd = n0 + nn;
            if (nd < N_NODES) {
                uint2 u = __ldg(H + (size_t)nd * 16 + (k4 >> 2));
                float2 a = __half22float2(*(__half2*)&u.x);
                float2 b = __half22float2(*(__half2*)&u.y);
                h[nn] = make_float4(a.x, a.y, b.x, b.y);
            } else h[nn] = make_float4(0.f, 0.f, 0.f, 0.f);
        }
#pragma unroll
        for (int j = 0; j < 10; j++) {
            float4 wv = *(const float4*)&sW2t[(j0 + j) * PADK + k4];
#pragma unroll
            for (int nn = 0; nn < 4; nn++)
                acc[nn][j] += h[nn].x * wv.x + h[nn].y * wv.y + h[nn].z * wv.z + h[nn].w * wv.w;
        }
    }
    unsigned short* Z = (unsigned short*)g_z1h;
#pragma unroll
    for (int nn = 0; nn < 4; nn++) {
        int nd = n0 + nn;
        if (nd >= N_NODES) break;
        unsigned* zp = (unsigned*)(Z + (size_t)nd * NLAB + j0);
#pragma unroll
        for (int j = 0; j < 10; j += 2) {
            __half2 hp = __floats2half2_rn(acc[nn][j], acc[nn][j + 1]);
            zp[j >> 1] = *(unsigned*)&hp;
        }
    }
}

// ---------------- final propagate + fused log-softmax (8-lane groups, 5 active) --------
__global__ __launch_bounds__(256) void k_edge40_lsm(float* __restrict__ out) {
    int tid = threadIdx.x;
    int row = blockIdx.x * 32 + (tid >> 3);
    int q = tid & 7;
    if (row >= N_NODES) return;
    int s = g_start[N_NODES + row];
    int n = g_cnt[N_NODES + row];
    bool act = (q < 5);
    const uint4* Z = (const uint4*)g_z1h;     // 5 uint4 per z row
    float4 accA = make_float4(0.f, 0.f, 0.f, 0.f);
    float4 accB = make_float4(0.f, 0.f, 0.f, 0.f);
    int i = 0;
    for (; i + 4 <= n; i += 4) {
        int2 p0 = __ldg(&g_ebuf[s + i]);
        int2 p1 = __ldg(&g_ebuf[s + i + 1]);
        int2 p2 = __ldg(&g_ebuf[s + i + 2]);
        int2 p3 = __ldg(&g_ebuf[s + i + 3]);
        if (act) {
            uint4 u0 = __ldg(Z + (size_t)p0.x * 5 + q);
            uint4 u1 = __ldg(Z + (size_t)p1.x * 5 + q);
            uint4 u2 = __ldg(Z + (size_t)p2.x * 5 + q);
            uint4 u3 = __ldg(Z + (size_t)p3.x * 5 + q);
            acc8(accA, accB, __int_as_float(p0.y), u0);
            acc8(accA, accB, __int_as_float(p1.y), u1);
            acc8(accA, accB, __int_as_float(p2.y), u2);
            acc8(accA, accB, __int_as_float(p3.y), u3);
        }
    }
    for (; i < n; i++) {
        int2 p = __ldg(&g_ebuf[s + i]);
        if (act) {
            uint4 u = __ldg(Z + (size_t)p.x * 5 + q);
            acc8(accA, accB, __int_as_float(p.y), u);
        }
    }
    // log-softmax across the 8-lane group (lanes 0..4 hold the 40 values)
    float m = act ? fmaxf(fmaxf(fmaxf(accA.x, accA.y), fmaxf(accA.z, accA.w)),
                          fmaxf(fmaxf(accB.x, accB.y), fmaxf(accB.z, accB.w))) : -1e30f;
#pragma unroll
    for (int o = 1; o < 8; o <<= 1) m = fmaxf(m, __shfl_xor_sync(0xFFFFFFFFu, m, o, 8));
    float es = act ? (expf(accA.x - m) + expf(accA.y - m) + expf(accA.z - m) + expf(accA.w - m) +
                      expf(accB.x - m) + expf(accB.y - m) + expf(accB.z - m) + expf(accB.w - m)) : 0.f;
#pragma unroll
    for (int o = 1; o < 8; o <<= 1) es += __shfl_xor_sync(0xFFFFFFFFu, es, o, 8);
    float l = m + logf(es);
    if (act) {
        float* op = out + (size_t)row * NLAB + q * 8;
        *(float4*)op = make_float4(accA.x - l, accA.y - l, accA.z - l, accA.w - l);
        *(float4*)(op + 4) = make_float4(accB.x - l, accB.y - l, accB.z - l, accB.w - l);
    }
    if (q == 0) g_cnt[N_NODES + row] = 0;     // restore invariant for next call
}

extern "C" void kernel_launch(void* const* d_in, const int* in_sizes, int n_in,
                              void* d_out, int out_size) {
    // Bind inputs by element count (pairwise distinct); indices are int32.
    const int* fi = 0; const float* fv = 0;
    const int* ei = 0; const float* ew = 0;
    const float *W1 = 0, *b1 = 0, *W2 = 0, *b2 = 0;
    int nnz = 0, ne = 0;
    for (int i = 0; i < n_in; i++) {
        int s = in_sizes[i];
        const void* p = d_in[i];
        if (s == 2 * MAX_NNZ)            { fi = (const int*)p; }
        else if (s == MAX_NNZ)           { fv = (const float*)p; nnz = s; }
        else if (s == 2 * MAX_NE)        { ei = (const int*)p; }
        else if (s == MAX_NE)            { ew = (const float*)p; ne = s; }
        else if (s == N_FEATS * HID)     { W1 = (const float*)p; }
        else if (s == HID)               { b1 = (const float*)p; }
        else if (s == HID * NLAB)        { W2 = (const float*)p; }
        else if (s == NLAB)              { b2 = (const float*)p; }
    }
    float* out = (float*)d_out;
    int tot = nnz + ne;

    // CSR build (g_cnt arrives all-zero: first call by static init, later calls
    // restored by k_feat_csr / k_edge40_lsm of the previous call)
    k_hist<<<(tot + 255) / 256, 256>>>(fi, nnz, ei, ne, W1);
    k_scan<<<250, 800>>>();
    k_scat<<<(tot + 255) / 256, 256>>>(fi, fv, nnz, ei, ew, ne);

    // GCN forward (gather-only, no atomics)
    k_feat_csr<<<(N_NODES + 31) / 32, 256>>>(b1);
    k_edge64_csr<<<(N_NODES + 31) / 32, 256>>>();
    k_dense<<<(N_NODES + 255) / 256, 256>>>(W2, b2);
    k_edge40_lsm<<<(N_NODES + 31) / 32, 256>>>(out);
}